// round 7
// baseline (speedup 1.0000x reference)
#include <cuda_runtime.h>
#include <cuda_bf16.h>
#include <math.h>
#include <stdint.h>

// Problem constants
#define D_MODEL 1024
#define D_INNER 2048
#define D_STATE 16
#define DT_RANK 64
#define D_CONV  4
#define BB      2
#define LL      1024
#define BL      (BB * LL)                 // 2048 rows
#define KS      8                         // split-K for x_proj

// ---------------------------------------------------------------------------
// Device scratch. 3-segment K-concat split (K' = 3K):
//   activations: [hi | lo | hi],  weights: [hi | hi | lo]
//   A'.W'^T = ahi*whi + alo*whi + ahi*wlo  (3-term compensated product)
// ---------------------------------------------------------------------------
__device__ float          g_xz[BL * 4096];
__device__ float          g_xc[BL * 2048];
__device__ __nv_bfloat16  g_xcs[BL * 6144];
__device__ float          g_xpart[KS * BL * 128];
__device__ float          g_xdbl[BL * 128];
__device__ __nv_bfloat16  g_dtA[BL * 192];
__device__ float          g_delta[BL * 2048];
__device__ __nv_bfloat16  g_ys[BL * 6144];
__device__ __nv_bfloat16  g_xs[BL * 3072];
__device__ __nv_bfloat16  g_wi[4096 * 3072];
__device__ __nv_bfloat16  g_wo[1024 * 6144];
__device__ __nv_bfloat16  g_wx[128 * 6144];
__device__ __nv_bfloat16  g_wdt[2048 * 192];

// ---------------------------------------------------------------------------
// helpers
// ---------------------------------------------------------------------------
__device__ __forceinline__ void cvt_pair(float x, float y,
                                         uint32_t& hi, uint32_t& lo) {
    asm("cvt.rn.bf16x2.f32 %0, %1, %2;" : "=r"(hi) : "f"(y), "f"(x));
    const float hx = __uint_as_float(hi << 16);
    const float hy = __uint_as_float(hi & 0xFFFF0000u);
    asm("cvt.rn.bf16x2.f32 %0, %1, %2;" : "=r"(lo) : "f"(y - hy), "f"(x - hx));
}

__device__ __forceinline__ void cp16(uint32_t s, const void* g) {
    asm volatile("cp.async.cg.shared.global [%0], [%1], 16;" :: "r"(s), "l"(g));
}
__device__ __forceinline__ void cp_commit() {
    asm volatile("cp.async.commit_group;");
}
__device__ __forceinline__ void cp_wait3() {
    asm volatile("cp.async.wait_group 3;" ::: "memory");
}

#define LDSM_X4(r0, r1, r2, r3, addr) \
    asm volatile("ldmatrix.sync.aligned.m8n8.x4.shared.b16 {%0,%1,%2,%3}, [%4];" \
                 : "=r"(r0), "=r"(r1), "=r"(r2), "=r"(r3) : "r"(addr))

__device__ __forceinline__ void mma_bf16(float (&c)[4],
                                         uint32_t a0, uint32_t a1,
                                         uint32_t a2, uint32_t a3,
                                         uint32_t b0, uint32_t b1) {
    asm volatile(
        "mma.sync.aligned.m16n8k16.row.col.f32.bf16.bf16.f32 "
        "{%0,%1,%2,%3},{%4,%5,%6,%7},{%8,%9},{%0,%1,%2,%3};"
        : "+f"(c[0]), "+f"(c[1]), "+f"(c[2]), "+f"(c[3])
        : "r"(a0), "r"(a1), "r"(a2), "r"(a3), "r"(b0), "r"(b1));
}

// ---------------------------------------------------------------------------
// bf16 HGEMM (pre-split operands):
//   C[M,N] = A[M,K'](lda) * W[N,K'](ldw)^T, bf16 in, f32 out.
// BM=BN=128, BK=64 bf16 (128B rows). 512 threads = 16 warps (4x4 grid),
// warp tile 32x32 (acc=32 regs, frags=16 -> no spill pressure).
// 5-stage cp.async ring, constant 4 groups in flight (empty-commit trick).
// EPI==1: +bias then softplus. Split-K via blockIdx.z (k-offset z*T*64,
// C += z*czstride). Requires M%128==0, N%128==0, K'%64==0 per split.
// ---------------------------------------------------------------------------
template<int EPI>
__global__ void __launch_bounds__(512)
hgemm(const __nv_bfloat16* __restrict__ A, const __nv_bfloat16* __restrict__ W,
      float* __restrict__ C, int lda, int ldw, int ldc, int T,
      long czstride, const float* __restrict__ bias)
{
    constexpr int S = 5;                  // stages
    extern __shared__ __align__(16) char smem[];
    const uint32_t smA0 = (uint32_t)__cvta_generic_to_shared(smem);
    const uint32_t smB0 = smA0 + S * 16384;

    const int tid  = threadIdx.x;
    const int wid  = tid >> 5;
    const int lane = tid & 31;
    const int wm   = wid >> 2;        // 0..3
    const int wn   = wid & 3;         // 0..3
    const int l16  = lane & 15;
    const int chal = lane >> 4;       // 0,1

    const long blockM = (long)blockIdx.y * 128;
    const long blockN = (long)blockIdx.x * 128;
    const int  koff   = blockIdx.z * T * 64;

    const __nv_bfloat16* Ab = A + blockM * lda + koff;
    const __nv_bfloat16* Wb = W + blockN * ldw + koff;

    // cp.async mapping: 8 threads per 128B row, 2 row-passes over 128 rows
    const int crow = tid >> 3;        // 0..63
    const int ccc  = tid & 7;

    // ldmatrix fragment bases
    uint32_t aoff[2], asw[2], boff[2], bsw[2];
#pragma unroll
    for (int mi = 0; mi < 2; mi++) {
        const int r = wm * 32 + mi * 16 + l16;
        aoff[mi] = r * 128;
        asw[mi]  = r & 7;
    }
#pragma unroll
    for (int ni = 0; ni < 2; ni++) {
        const int r = wn * 32 + ni * 16 + l16;
        boff[ni] = r * 128;
        bsw[ni]  = r & 7;
    }

    float acc[2][4][4];
#pragma unroll
    for (int mi = 0; mi < 2; mi++)
#pragma unroll
        for (int n8 = 0; n8 < 4; n8++)
#pragma unroll
            for (int j = 0; j < 4; j++) acc[mi][n8][j] = 0.f;

    auto issue = [&](int s, int t) {
        const int k0 = t * 64;
        const uint32_t dA = smA0 + s * 16384;
        const uint32_t dB = smB0 + s * 16384;
#pragma unroll
        for (int p = 0; p < 2; p++) {
            const int row = crow + p * 64;
            const int scc = ccc ^ (row & 7);
            cp16(dA + row * 128 + scc * 16, Ab + (long)row * lda + k0 + ccc * 8);
            cp16(dB + row * 128 + scc * 16, Wb + (long)row * ldw + k0 + ccc * 8);
        }
    };

    // prologue: always commit 4 groups (empty commits keep the count exact)
#pragma unroll
    for (int i = 0; i < 4; i++) {
        if (i < T) issue(i, i);
        cp_commit();
    }

    for (int t = 0; t < T; t++) {
        cp_wait3();          // oldest of 4 in-flight groups (= tile t) done
        __syncthreads();     // previous compute fully drained before reuse
        const int nt = t + 4;
        if (nt < T) issue(nt % S, nt);
        cp_commit();

        const uint32_t sA = smA0 + (t % S) * 16384;
        const uint32_t sB = smB0 + (t % S) * 16384;
#pragma unroll
        for (int k16 = 0; k16 < 4; k16++) {
            const uint32_t ch = (uint32_t)(k16 * 2 + chal);
            uint32_t a[2][4], b[2][4];
#pragma unroll
            for (int mi = 0; mi < 2; mi++)
                LDSM_X4(a[mi][0], a[mi][1], a[mi][2], a[mi][3],
                        sA + aoff[mi] + ((ch ^ asw[mi]) << 4));
#pragma unroll
            for (int ni = 0; ni < 2; ni++)
                LDSM_X4(b[ni][0], b[ni][1], b[ni][2], b[ni][3],
                        sB + boff[ni] + ((ch ^ bsw[ni]) << 4));
#pragma unroll
            for (int mi = 0; mi < 2; mi++)
#pragma unroll
                for (int n8 = 0; n8 < 4; n8++) {
                    const int np = n8 >> 1;
                    const uint32_t b0 = (n8 & 1) ? b[np][1] : b[np][0];
                    const uint32_t b1 = (n8 & 1) ? b[np][3] : b[np][2];
                    mma_bf16(acc[mi][n8],
                             a[mi][0], a[mi][1], a[mi][2], a[mi][3], b0, b1);
                }
        }
    }

    // epilogue
    float* Cb = C + (long)blockIdx.z * czstride;
    const int er = lane >> 2;
    const int ec = (lane & 3) * 2;
#pragma unroll
    for (int mi = 0; mi < 2; mi++) {
#pragma unroll
        for (int n8 = 0; n8 < 4; n8++) {
            const long row = blockM + wm * 32 + mi * 16 + er;
            const int  col = (int)blockN + wn * 32 + n8 * 8 + ec;
            float v0 = acc[mi][n8][0], v1 = acc[mi][n8][1];
            float v2 = acc[mi][n8][2], v3 = acc[mi][n8][3];
            if (EPI == 1) {
                const float b0 = bias[col], b1 = bias[col + 1];
                v0 += b0; v1 += b1; v2 += b0; v3 += b1;
                v0 = (v0 > 20.f) ? v0 : log1pf(expf(v0));
                v1 = (v1 > 20.f) ? v1 : log1pf(expf(v1));
                v2 = (v2 > 20.f) ? v2 : log1pf(expf(v2));
                v3 = (v3 > 20.f) ? v3 : log1pf(expf(v3));
            }
            *(float2*)&Cb[row * ldc + col]       = make_float2(v0, v1);
            *(float2*)&Cb[(row + 8) * ldc + col] = make_float2(v2, v3);
        }
    }
}

// ---------------------------------------------------------------------------
// f32 -> bf16 3-segment split, row stride 3K.
//   ACT==1 (activations): [hi | lo | hi], ACT==0 (weights): [hi | hi | lo]
// ---------------------------------------------------------------------------
__device__ __forceinline__ void split_body(const float* __restrict__ in,
                                           __nv_bfloat16* __restrict__ out,
                                           int K, int li, int inRows, int act)
{
    const int e   = li * 4;
    const int row = e / K;
    const int k   = e - row * K;
    float4 v = make_float4(0.f, 0.f, 0.f, 0.f);
    if (row < inRows) v = *(const float4*)(in + (long)row * K + k);
    uint32_t h01, l01, h23, l23;
    cvt_pair(v.x, v.y, h01, l01);
    cvt_pair(v.z, v.w, h23, l23);
    __nv_bfloat16* o = out + (long)row * 3 * K + k;
    const uint2 hv = make_uint2(h01, h23);
    const uint2 lv = make_uint2(l01, l23);
    if (act) {
        *(uint2*)o           = hv;
        *(uint2*)(o + K)     = lv;
        *(uint2*)(o + 2 * K) = hv;
    } else {
        *(uint2*)o           = hv;
        *(uint2*)(o + K)     = hv;
        *(uint2*)(o + 2 * K) = lv;
    }
}

template<int ACT>
__global__ void split_kernel(const float* __restrict__ in,
                             __nv_bfloat16* __restrict__ out,
                             int K, int n4, int inRows)
{
    const int i = blockIdx.x * 256 + threadIdx.x;
    if (i >= n4) return;
    split_body(in, out, K, i, inRows, ACT);
}

// Fused split of out_proj (1024x2048), x_proj (96->128 x2048), dt_proj (2048x64)
#define N4_WO (1024 * 2048 / 4)
#define N4_WX (128 * 2048 / 4)
#define N4_WDT (2048 * 64 / 4)
__global__ void split_rest(const float* __restrict__ wo_in,
                           const float* __restrict__ wx_in,
                           const float* __restrict__ wdt_in,
                           __nv_bfloat16* __restrict__ wo,
                           __nv_bfloat16* __restrict__ wx,
                           __nv_bfloat16* __restrict__ wdt)
{
    const int i = blockIdx.x * 256 + threadIdx.x;
    if (i < N4_WO) {
        split_body(wo_in, wo, 2048, i, 1024, 0);
    } else if (i < N4_WO + N4_WX) {
        split_body(wx_in, wx, 2048, i - N4_WO, 96, 0);
    } else if (i < N4_WO + N4_WX + N4_WDT) {
        split_body(wdt_in, wdt, 64, i - N4_WO - N4_WX, 2048, 0);
    }
}

// ---------------------------------------------------------------------------
// Split-K reduce for x_proj partials + dt-row act-split (K=64 -> [hi|lo|hi])
// ---------------------------------------------------------------------------
__global__ void reduce_split(const float* __restrict__ p,
                             float* __restrict__ xdbl,
                             __nv_bfloat16* __restrict__ dtA)
{
    const int n4 = BL * 128 / 4;
    const int i = blockIdx.x * 256 + threadIdx.x;
    if (i >= n4) return;
    float4 a = ((const float4*)p)[i];
#pragma unroll
    for (int s = 1; s < KS; s++) {
        const float4 b = ((const float4*)p)[(long)s * n4 + i];
        a.x += b.x; a.y += b.y; a.z += b.z; a.w += b.w;
    }
    ((float4*)xdbl)[i] = a;
    const int e = i * 4;
    const int col = e & 127;
    if (col < 64) {
        const int row = e >> 7;
        uint32_t h01, l01, h23, l23;
        cvt_pair(a.x, a.y, h01, l01);
        cvt_pair(a.z, a.w, h23, l23);
        __nv_bfloat16* o = dtA + (long)row * 192 + col;
        const uint2 hv = make_uint2(h01, h23);
        *(uint2*)o         = hv;
        *(uint2*)(o + 64)  = make_uint2(l01, l23);
        *(uint2*)(o + 128) = hv;
    }
}

// ---------------------------------------------------------------------------
// Depthwise causal conv (k=4) + bias + SiLU; writes f32 + act-split bf16
// ---------------------------------------------------------------------------
__global__ void conv_silu_kernel(const float* __restrict__ xz,
                                 const float* __restrict__ cw,
                                 const float* __restrict__ cb,
                                 float* __restrict__ xc,
                                 __nv_bfloat16* __restrict__ xcs)
{
    const int idx = blockIdx.x * blockDim.x + threadIdx.x;
    if (idx >= BL * D_INNER) return;
    const int d = idx & (D_INNER - 1);
    const int r = idx >> 11;
    const int l = r & (LL - 1);
    const int b = r >> 10;

    float acc = cb[d];
#pragma unroll
    for (int i = 0; i < D_CONV; i++) {
        const int ll = l - (D_CONV - 1) + i;
        if (ll >= 0)
            acc = fmaf(xz[((long)(b * LL + ll)) * 4096 + d],
                       cw[d * D_CONV + i], acc);
    }
    const float s = acc / (1.f + expf(-acc));
    xc[idx] = s;
    const __nv_bfloat16 h = __float2bfloat16(s);
    __nv_bfloat16* o = xcs + (long)r * 6144 + d;
    o[0]    = h;
    o[2048] = __float2bfloat16(s - __bfloat162float(h));
    o[4096] = h;
}

// ---------------------------------------------------------------------------
// Selective scan + D skip + SiLU(z) gating; writes y as act-split bf16
// ---------------------------------------------------------------------------
__global__ void scan_kernel(const float* __restrict__ delta,
                            const float* __restrict__ xdbl,
                            const float* __restrict__ xc,
                            const float* __restrict__ xz,
                            const float* __restrict__ A_log,
                            const float* __restrict__ Dv,
                            __nv_bfloat16* __restrict__ ys)
{
    const int t    = blockIdx.x * blockDim.x + threadIdx.x;
    const int lane = t & 15;
    const int g    = t >> 4;
    const int d    = g & (D_INNER - 1);
    const int b    = g >> 11;

    const float Aval = -expf(A_log[d * D_STATE + lane]);
    const float Dd   = Dv[d];

    const float* dp  = delta + ((long)b << 21) + d;
    const float* xcp = xc    + ((long)b << 21) + d;
    const float* xdp = xdbl  + (long)b * LL * 128;
    const float* zp  = xz    + ((long)b << 22) + D_INNER + d;

    float h = 0.f;
    for (int l = 0; l < LL; l++) {
        const float dl  = dp[(long)l << 11];
        const float xcv = xcp[(long)l << 11];
        const float Bv  = xdp[l * 128 + 64 + lane];
        const float Cv  = xdp[l * 128 + 80 + lane];

        const float dA = expf(dl * Aval);
        h = fmaf(dA, h, dl * Bv * xcv);

        float p = h * Cv;
        p += __shfl_xor_sync(0xffffffffu, p, 8);
        p += __shfl_xor_sync(0xffffffffu, p, 4);
        p += __shfl_xor_sync(0xffffffffu, p, 2);
        p += __shfl_xor_sync(0xffffffffu, p, 1);

        if (lane == 0) {
            const float zv  = zp[(long)l << 12];
            const float sig = 1.f / (1.f + expf(-zv));
            const float yv  = (p + xcv * Dd) * (zv * sig);
            const long  row = (long)b * LL + l;
            const __nv_bfloat16 hh = __float2bfloat16(yv);
            __nv_bfloat16* o = ys + row * 6144 + d;
            o[0]    = hh;
            o[2048] = __float2bfloat16(yv - __bfloat162float(hh));
            o[4096] = hh;
        }
    }
}

// ---------------------------------------------------------------------------
// Launch
// ---------------------------------------------------------------------------
extern "C" void kernel_launch(void* const* d_in, const int* in_sizes, int n_in,
                              void* d_out, int out_size)
{
    const float* x         = (const float*)d_in[0];
    const float* in_proj_w = (const float*)d_in[1];
    const float* conv_w    = (const float*)d_in[2];
    const float* conv_b    = (const float*)d_in[3];
    const float* x_proj_w  = (const float*)d_in[4];
    const float* dt_proj_w = (const float*)d_in[5];
    const float* dt_proj_b = (const float*)d_in[6];
    const float* A_log     = (const float*)d_in[7];
    const float* Dv        = (const float*)d_in[8];
    const float* out_proj  = (const float*)d_in[9];
    float* out = (float*)d_out;

    float *xz, *xc, *xpart, *xdbl, *delta;
    __nv_bfloat16 *xcs, *dtA, *ys, *xs, *wi, *wo, *wx, *wdt;
    cudaGetSymbolAddress((void**)&xz,    g_xz);
    cudaGetSymbolAddress((void**)&xc,    g_xc);
    cudaGetSymbolAddress((void**)&xcs,   g_xcs);
    cudaGetSymbolAddress((void**)&xpart, g_xpart);
    cudaGetSymbolAddress((void**)&xdbl,  g_xdbl);
    cudaGetSymbolAddress((void**)&dtA,   g_dtA);
    cudaGetSymbolAddress((void**)&delta, g_delta);
    cudaGetSymbolAddress((void**)&ys,    g_ys);
    cudaGetSymbolAddress((void**)&xs,    g_xs);
    cudaGetSymbolAddress((void**)&wi,    g_wi);
    cudaGetSymbolAddress((void**)&wo,    g_wo);
    cudaGetSymbolAddress((void**)&wx,    g_wx);
    cudaGetSymbolAddress((void**)&wdt,   g_wdt);

    const int SMEM_SZ = 10 * 16384;   // 160 KB (5-stage double ring)
    static bool attr_set = false;
    if (!attr_set) {
        cudaFuncSetAttribute(hgemm<0>, cudaFuncAttributeMaxDynamicSharedMemorySize, SMEM_SZ);
        cudaFuncSetAttribute(hgemm<1>, cudaFuncAttributeMaxDynamicSharedMemorySize, SMEM_SZ);
        attr_set = true;
    }

    // launch 0: x act-split
    split_kernel<1><<<(BL * 1024 / 4 + 255) / 256, 256>>>(x, xs, 1024, BL * 1024 / 4, BL);
    // launch 1: in_proj_w wt-split
    split_kernel<0><<<(4096 * 1024 / 4 + 255) / 256, 256>>>(in_proj_w, wi, 1024, 4096 * 1024 / 4, 4096);
    // launch 2: remaining weight splits (fused)
    split_rest<<<(N4_WO + N4_WX + N4_WDT + 255) / 256, 256>>>(
        out_proj, x_proj_w, dt_proj_w, wo, wx, wdt);

    // launch 3 (ncu -s 5 target): xz = x @ in_proj_w.T  (M=2048,N=4096,K'=3072)
    hgemm<0><<<dim3(32, 16, 1), 512, SMEM_SZ>>>(
        xs, wi, xz, 3072, 3072, 4096, 48, 0, nullptr);

    // launch 4: conv + silu (+ act-split)
    conv_silu_kernel<<<(BL * D_INNER + 255) / 256, 256>>>(xz, conv_w, conv_b, xc, xcs);

    // launch 5: x_dbl partials (M=2048, N=128pad, K'=6144), split-K=8
    hgemm<0><<<dim3(1, 16, KS), 512, SMEM_SZ>>>(
        xcs, wx, xpart, 6144, 6144, 128, 6144 / KS / 64, (long)BL * 128, nullptr);
    // launch 6: reduce + dt act-split
    reduce_split<<<(BL * 128 / 4 + 255) / 256, 256>>>(xpart, xdbl, dtA);

    // launch 7: delta = softplus(dt @ dt_proj_w.T + b)  (M=2048,N=2048,K'=192)
    hgemm<1><<<dim3(16, 16, 1), 512, SMEM_SZ>>>(
        dtA, wdt, delta, 192, 192, 2048, 3, 0, dt_proj_b);

    // launch 8: selective scan + gating (+ y act-split)
    scan_kernel<<<(BB * D_INNER * D_STATE) / 256, 256>>>(
        delta, xdbl, xc, xz, A_log, Dv, ys);

    // launch 9: out = y @ out_proj_w.T  (M=2048, N=1024, K'=6144)
    hgemm<0><<<dim3(8, 16, 1), 512, SMEM_SZ>>>(
        ys, wo, out, 6144, 6144, 1024, 96, 0, nullptr);
}

// round 8
// speedup vs baseline: 2.2958x; 2.2958x over previous
#include <cuda_runtime.h>
#include <cuda_bf16.h>
#include <math.h>
#include <stdint.h>

// Problem constants
#define D_MODEL 1024
#define D_INNER 2048
#define D_STATE 16
#define DT_RANK 64
#define D_CONV  4
#define BB      2
#define LL      1024
#define BL      (BB * LL)                 // 2048 rows
#define KS      8                         // split-K for x_proj
#define NCH     8                         // scan chunks
#define CHL     (LL / NCH)                // 128 steps per chunk

// ---------------------------------------------------------------------------
// Device scratch. 3-segment K-concat split (K' = 3K):
//   activations: [hi | lo | hi],  weights: [hi | hi | lo]
// ---------------------------------------------------------------------------
__device__ float          g_xz[BL * 4096];
__device__ float          g_xc[BL * 2048];
__device__ __nv_bfloat16  g_xcs[BL * 6144];
__device__ float          g_xpart[KS * BL * 128];
__device__ float          g_xdbl[BL * 128];
__device__ __nv_bfloat16  g_dtA[BL * 192];
__device__ float          g_delta[BL * 2048];
__device__ __nv_bfloat16  g_ys[BL * 6144];
__device__ __nv_bfloat16  g_xs[BL * 3072];
__device__ __nv_bfloat16  g_wi[4096 * 3072];
__device__ __nv_bfloat16  g_wo[1024 * 6144];
__device__ __nv_bfloat16  g_wx[128 * 6144];
__device__ __nv_bfloat16  g_wdt[2048 * 192];
// chunked-scan intermediates: [b][chunk][d][n]
__device__ float          g_S[BB * NCH * D_INNER * D_STATE];
__device__ float          g_P[BB * NCH * D_INNER * D_STATE];
__device__ float          g_Hc[BB * NCH * D_INNER * D_STATE];

// ---------------------------------------------------------------------------
// helpers
// ---------------------------------------------------------------------------
__device__ __forceinline__ void cvt_pair(float x, float y,
                                         uint32_t& hi, uint32_t& lo) {
    asm("cvt.rn.bf16x2.f32 %0, %1, %2;" : "=r"(hi) : "f"(y), "f"(x));
    const float hx = __uint_as_float(hi << 16);
    const float hy = __uint_as_float(hi & 0xFFFF0000u);
    asm("cvt.rn.bf16x2.f32 %0, %1, %2;" : "=r"(lo) : "f"(y - hy), "f"(x - hx));
}

__device__ __forceinline__ void cp16(uint32_t s, const void* g) {
    asm volatile("cp.async.cg.shared.global [%0], [%1], 16;" :: "r"(s), "l"(g));
}
__device__ __forceinline__ void cp_commit() {
    asm volatile("cp.async.commit_group;");
}
__device__ __forceinline__ void cp_wait1() {
    asm volatile("cp.async.wait_group 1;" ::: "memory");
}

#define LDSM_X4(r0, r1, r2, r3, addr) \
    asm volatile("ldmatrix.sync.aligned.m8n8.x4.shared.b16 {%0,%1,%2,%3}, [%4];" \
                 : "=r"(r0), "=r"(r1), "=r"(r2), "=r"(r3) : "r"(addr))

__device__ __forceinline__ void mma_bf16(float (&c)[4],
                                         uint32_t a0, uint32_t a1,
                                         uint32_t a2, uint32_t a3,
                                         uint32_t b0, uint32_t b1) {
    asm volatile(
        "mma.sync.aligned.m16n8k16.row.col.f32.bf16.bf16.f32 "
        "{%0,%1,%2,%3},{%4,%5,%6,%7},{%8,%9},{%0,%1,%2,%3};"
        : "+f"(c[0]), "+f"(c[1]), "+f"(c[2]), "+f"(c[3])
        : "r"(a0), "r"(a1), "r"(a2), "r"(a3), "r"(b0), "r"(b1));
}

// ---------------------------------------------------------------------------
// bf16 HGEMM (pre-split operands):
//   C[M,N] = A[M,K'](lda) * W[N,K'](ldw)^T, bf16 in, f32 out.
// BM=BN=128, BK=64 bf16 (128B rows). 512 threads = 16 warps (4x4),
// warp tile 32x32. 3-stage cp.async ring (96KB smem -> 2 CTAs/SM).
// EPI==1: +bias then softplus. Split-K via blockIdx.z.
// Requires M%128==0, N%128==0, K'%64==0 per split, T>=2.
// ---------------------------------------------------------------------------
template<int EPI>
__global__ void __launch_bounds__(512, 2)
hgemm(const __nv_bfloat16* __restrict__ A, const __nv_bfloat16* __restrict__ W,
      float* __restrict__ C, int lda, int ldw, int ldc, int T,
      long czstride, const float* __restrict__ bias)
{
    constexpr int S = 3;
    extern __shared__ __align__(16) char smem[];
    const uint32_t smA0 = (uint32_t)__cvta_generic_to_shared(smem);
    const uint32_t smB0 = smA0 + S * 16384;

    const int tid  = threadIdx.x;
    const int wid  = tid >> 5;
    const int lane = tid & 31;
    const int wm   = wid >> 2;
    const int wn   = wid & 3;
    const int l16  = lane & 15;
    const int chal = lane >> 4;

    const long blockM = (long)blockIdx.y * 128;
    const long blockN = (long)blockIdx.x * 128;
    const int  koff   = blockIdx.z * T * 64;

    const __nv_bfloat16* Ab = A + blockM * lda + koff;
    const __nv_bfloat16* Wb = W + blockN * ldw + koff;

    const int crow = tid >> 3;        // 0..63
    const int ccc  = tid & 7;

    uint32_t aoff[2], asw[2], boff[2], bsw[2];
#pragma unroll
    for (int mi = 0; mi < 2; mi++) {
        const int r = wm * 32 + mi * 16 + l16;
        aoff[mi] = r * 128;
        asw[mi]  = r & 7;
    }
#pragma unroll
    for (int ni = 0; ni < 2; ni++) {
        const int r = wn * 32 + ni * 16 + l16;
        boff[ni] = r * 128;
        bsw[ni]  = r & 7;
    }

    float acc[2][4][4];
#pragma unroll
    for (int mi = 0; mi < 2; mi++)
#pragma unroll
        for (int n8 = 0; n8 < 4; n8++)
#pragma unroll
            for (int j = 0; j < 4; j++) acc[mi][n8][j] = 0.f;

    auto issue = [&](int s, int t) {
        const int k0 = t * 64;
        const uint32_t dA = smA0 + s * 16384;
        const uint32_t dB = smB0 + s * 16384;
#pragma unroll
        for (int p = 0; p < 2; p++) {
            const int row = crow + p * 64;
            const int scc = ccc ^ (row & 7);
            cp16(dA + row * 128 + scc * 16, Ab + (long)row * lda + k0 + ccc * 8);
            cp16(dB + row * 128 + scc * 16, Wb + (long)row * ldw + k0 + ccc * 8);
        }
    };

    issue(0, 0);
    cp_commit();
    issue(1, 1);
    cp_commit();

    for (int t = 0; t < T; t++) {
        cp_wait1();
        __syncthreads();
        const int nt = t + 2;
        if (nt < T) issue(nt % S, nt);
        cp_commit();

        const uint32_t sA = smA0 + (t % S) * 16384;
        const uint32_t sB = smB0 + (t % S) * 16384;
#pragma unroll
        for (int k16 = 0; k16 < 4; k16++) {
            const uint32_t ch = (uint32_t)(k16 * 2 + chal);
            uint32_t a[2][4], b[2][4];
#pragma unroll
            for (int mi = 0; mi < 2; mi++)
                LDSM_X4(a[mi][0], a[mi][1], a[mi][2], a[mi][3],
                        sA + aoff[mi] + ((ch ^ asw[mi]) << 4));
#pragma unroll
            for (int ni = 0; ni < 2; ni++)
                LDSM_X4(b[ni][0], b[ni][1], b[ni][2], b[ni][3],
                        sB + boff[ni] + ((ch ^ bsw[ni]) << 4));
#pragma unroll
            for (int mi = 0; mi < 2; mi++)
#pragma unroll
                for (int n8 = 0; n8 < 4; n8++) {
                    const int np = n8 >> 1;
                    const uint32_t b0 = (n8 & 1) ? b[np][1] : b[np][0];
                    const uint32_t b1 = (n8 & 1) ? b[np][3] : b[np][2];
                    mma_bf16(acc[mi][n8],
                             a[mi][0], a[mi][1], a[mi][2], a[mi][3], b0, b1);
                }
        }
    }

    float* Cb = C + (long)blockIdx.z * czstride;
    const int er = lane >> 2;
    const int ec = (lane & 3) * 2;
#pragma unroll
    for (int mi = 0; mi < 2; mi++) {
#pragma unroll
        for (int n8 = 0; n8 < 4; n8++) {
            const long row = blockM + wm * 32 + mi * 16 + er;
            const int  col = (int)blockN + wn * 32 + n8 * 8 + ec;
            float v0 = acc[mi][n8][0], v1 = acc[mi][n8][1];
            float v2 = acc[mi][n8][2], v3 = acc[mi][n8][3];
            if (EPI == 1) {
                const float b0 = bias[col], b1 = bias[col + 1];
                v0 += b0; v1 += b1; v2 += b0; v3 += b1;
                v0 = (v0 > 20.f) ? v0 : log1pf(expf(v0));
                v1 = (v1 > 20.f) ? v1 : log1pf(expf(v1));
                v2 = (v2 > 20.f) ? v2 : log1pf(expf(v2));
                v3 = (v3 > 20.f) ? v3 : log1pf(expf(v3));
            }
            *(float2*)&Cb[row * ldc + col]       = make_float2(v0, v1);
            *(float2*)&Cb[(row + 8) * ldc + col] = make_float2(v2, v3);
        }
    }
}

// ---------------------------------------------------------------------------
// f32 -> bf16 3-segment split
// ---------------------------------------------------------------------------
__device__ __forceinline__ void split_body(const float* __restrict__ in,
                                           __nv_bfloat16* __restrict__ out,
                                           int K, int li, int inRows, int act)
{
    const int e   = li * 4;
    const int row = e / K;
    const int k   = e - row * K;
    float4 v = make_float4(0.f, 0.f, 0.f, 0.f);
    if (row < inRows) v = *(const float4*)(in + (long)row * K + k);
    uint32_t h01, l01, h23, l23;
    cvt_pair(v.x, v.y, h01, l01);
    cvt_pair(v.z, v.w, h23, l23);
    __nv_bfloat16* o = out + (long)row * 3 * K + k;
    const uint2 hv = make_uint2(h01, h23);
    const uint2 lv = make_uint2(l01, l23);
    if (act) {
        *(uint2*)o           = hv;
        *(uint2*)(o + K)     = lv;
        *(uint2*)(o + 2 * K) = hv;
    } else {
        *(uint2*)o           = hv;
        *(uint2*)(o + K)     = hv;
        *(uint2*)(o + 2 * K) = lv;
    }
}

template<int ACT>
__global__ void split_kernel(const float* __restrict__ in,
                             __nv_bfloat16* __restrict__ out,
                             int K, int n4, int inRows)
{
    const int i = blockIdx.x * 256 + threadIdx.x;
    if (i >= n4) return;
    split_body(in, out, K, i, inRows, ACT);
}

#define N4_WO (1024 * 2048 / 4)
#define N4_WX (128 * 2048 / 4)
#define N4_WDT (2048 * 64 / 4)
__global__ void split_rest(const float* __restrict__ wo_in,
                           const float* __restrict__ wx_in,
                           const float* __restrict__ wdt_in,
                           __nv_bfloat16* __restrict__ wo,
                           __nv_bfloat16* __restrict__ wx,
                           __nv_bfloat16* __restrict__ wdt)
{
    const int i = blockIdx.x * 256 + threadIdx.x;
    if (i < N4_WO) {
        split_body(wo_in, wo, 2048, i, 1024, 0);
    } else if (i < N4_WO + N4_WX) {
        split_body(wx_in, wx, 2048, i - N4_WO, 96, 0);
    } else if (i < N4_WO + N4_WX + N4_WDT) {
        split_body(wdt_in, wdt, 64, i - N4_WO - N4_WX, 2048, 0);
    }
}

// ---------------------------------------------------------------------------
// Split-K reduce for x_proj partials + dt-row act-split
// ---------------------------------------------------------------------------
__global__ void reduce_split(const float* __restrict__ p,
                             float* __restrict__ xdbl,
                             __nv_bfloat16* __restrict__ dtA)
{
    const int n4 = BL * 128 / 4;
    const int i = blockIdx.x * 256 + threadIdx.x;
    if (i >= n4) return;
    float4 a = ((const float4*)p)[i];
#pragma unroll
    for (int s = 1; s < KS; s++) {
        const float4 b = ((const float4*)p)[(long)s * n4 + i];
        a.x += b.x; a.y += b.y; a.z += b.z; a.w += b.w;
    }
    ((float4*)xdbl)[i] = a;
    const int e = i * 4;
    const int col = e & 127;
    if (col < 64) {
        const int row = e >> 7;
        uint32_t h01, l01, h23, l23;
        cvt_pair(a.x, a.y, h01, l01);
        cvt_pair(a.z, a.w, h23, l23);
        __nv_bfloat16* o = dtA + (long)row * 192 + col;
        const uint2 hv = make_uint2(h01, h23);
        *(uint2*)o         = hv;
        *(uint2*)(o + 64)  = make_uint2(l01, l23);
        *(uint2*)(o + 128) = hv;
    }
}

// ---------------------------------------------------------------------------
// Depthwise causal conv (k=4) + bias + SiLU; writes f32 + act-split bf16
// ---------------------------------------------------------------------------
__global__ void conv_silu_kernel(const float* __restrict__ xz,
                                 const float* __restrict__ cw,
                                 const float* __restrict__ cb,
                                 float* __restrict__ xc,
                                 __nv_bfloat16* __restrict__ xcs)
{
    const int idx = blockIdx.x * blockDim.x + threadIdx.x;
    if (idx >= BL * D_INNER) return;
    const int d = idx & (D_INNER - 1);
    const int r = idx >> 11;
    const int l = r & (LL - 1);
    const int b = r >> 10;

    float acc = cb[d];
#pragma unroll
    for (int i = 0; i < D_CONV; i++) {
        const int ll = l - (D_CONV - 1) + i;
        if (ll >= 0)
            acc = fmaf(xz[((long)(b * LL + ll)) * 4096 + d],
                       cw[d * D_CONV + i], acc);
    }
    const float s = acc / (1.f + expf(-acc));
    xc[idx] = s;
    const __nv_bfloat16 h = __float2bfloat16(s);
    __nv_bfloat16* o = xcs + (long)r * 6144 + d;
    o[0]    = h;
    o[2048] = __float2bfloat16(s - __bfloat162float(h));
    o[4096] = h;
}

// ---------------------------------------------------------------------------
// Chunked selective scan.
// Mapping (all passes): t = (b<<18)|(c<<15)|(d<<4)|n, arrays indexed by t.
// Pass A: per chunk, h from 0: S = final local state, P = prod of decays.
// Pass B: prefix over chunks -> carry-in state Hc per chunk.
// Pass C: re-run chunk seeded with Hc, emit gated y (act-split bf16).
// ---------------------------------------------------------------------------
__global__ void scan_pass_a(const float* __restrict__ delta,
                            const float* __restrict__ xdbl,
                            const float* __restrict__ xc,
                            const float* __restrict__ A_log,
                            float* __restrict__ Sarr,
                            float* __restrict__ Parr)
{
    const int t = blockIdx.x * 256 + threadIdx.x;   // 524288
    const int n = t & 15;
    const int g = t >> 4;
    const int d = g & (D_INNER - 1);
    const int c = (g >> 11) & (NCH - 1);
    const int b = g >> 14;

    const float Aval = -__expf(A_log[d * D_STATE + n]);
    const float* dp  = delta + ((long)b << 21) + d;
    const float* xcp = xc    + ((long)b << 21) + d;
    const float* xdp = xdbl  + (long)b * LL * 128;

    float h = 0.f, Pr = 1.f;
    const int l0 = c * CHL;
#pragma unroll 4
    for (int i = 0; i < CHL; i++) {
        const int l = l0 + i;
        const float dl  = dp[(long)l << 11];
        const float xcv = xcp[(long)l << 11];
        const float Bv  = xdp[l * 128 + 64 + n];
        const float a   = __expf(dl * Aval);
        Pr *= a;
        h = fmaf(a, h, dl * Bv * xcv);
    }
    Sarr[t] = h;
    Parr[t] = Pr;
}

__global__ void scan_pass_b(const float* __restrict__ Sarr,
                            const float* __restrict__ Parr,
                            float* __restrict__ Hc)
{
    const int t = blockIdx.x * 256 + threadIdx.x;   // 65536
    const int n = t & 15;
    const int d = (t >> 4) & (D_INNER - 1);
    const int b = t >> 15;
    float H = 0.f;
#pragma unroll
    for (int c = 0; c < NCH; c++) {
        const long idx = ((long)((b * NCH + c) * D_INNER + d) << 4) + n;
        Hc[idx] = H;
        H = fmaf(Parr[idx], H, Sarr[idx]);
    }
}

__global__ void scan_pass_c(const float* __restrict__ delta,
                            const float* __restrict__ xdbl,
                            const float* __restrict__ xc,
                            const float* __restrict__ xz,
                            const float* __restrict__ A_log,
                            const float* __restrict__ Dv,
                            const float* __restrict__ Hc,
                            __nv_bfloat16* __restrict__ ys)
{
    const int t = blockIdx.x * 256 + threadIdx.x;   // 524288
    const int n = t & 15;
    const int g = t >> 4;
    const int d = g & (D_INNER - 1);
    const int c = (g >> 11) & (NCH - 1);
    const int b = g >> 14;

    const float Aval = -__expf(A_log[d * D_STATE + n]);
    const float Dd   = Dv[d];

    const float* dp  = delta + ((long)b << 21) + d;
    const float* xcp = xc    + ((long)b << 21) + d;
    const float* xdp = xdbl  + (long)b * LL * 128;
    const float* zp  = xz    + ((long)b << 22) + D_INNER + d;

    float h = Hc[t];
    const int l0 = c * CHL;
    for (int i = 0; i < CHL; i++) {
        const int l = l0 + i;
        const float dl  = dp[(long)l << 11];
        const float xcv = xcp[(long)l << 11];
        const float Bv  = xdp[l * 128 + 64 + n];
        const float Cv  = xdp[l * 128 + 80 + n];

        const float a = __expf(dl * Aval);
        h = fmaf(a, h, dl * Bv * xcv);

        float p = h * Cv;
        p += __shfl_xor_sync(0xffffffffu, p, 8);
        p += __shfl_xor_sync(0xffffffffu, p, 4);
        p += __shfl_xor_sync(0xffffffffu, p, 2);
        p += __shfl_xor_sync(0xffffffffu, p, 1);

        if (n == 0) {
            const float zv  = zp[(long)l << 12];
            const float sig = 1.f / (1.f + __expf(-zv));
            const float yv  = (p + xcv * Dd) * (zv * sig);
            const long  row = (long)b * LL + l;
            const __nv_bfloat16 hh = __float2bfloat16(yv);
            __nv_bfloat16* o = ys + row * 6144 + d;
            o[0]    = hh;
            o[2048] = __float2bfloat16(yv - __bfloat162float(hh));
            o[4096] = hh;
        }
    }
}

// ---------------------------------------------------------------------------
// Launch
// ---------------------------------------------------------------------------
extern "C" void kernel_launch(void* const* d_in, const int* in_sizes, int n_in,
                              void* d_out, int out_size)
{
    const float* x         = (const float*)d_in[0];
    const float* in_proj_w = (const float*)d_in[1];
    const float* conv_w    = (const float*)d_in[2];
    const float* conv_b    = (const float*)d_in[3];
    const float* x_proj_w  = (const float*)d_in[4];
    const float* dt_proj_w = (const float*)d_in[5];
    const float* dt_proj_b = (const float*)d_in[6];
    const float* A_log     = (const float*)d_in[7];
    const float* Dv        = (const float*)d_in[8];
    const float* out_proj  = (const float*)d_in[9];
    float* out = (float*)d_out;

    float *xz, *xc, *xpart, *xdbl, *delta, *Sarr, *Parr, *Hc;
    __nv_bfloat16 *xcs, *dtA, *ys, *xs, *wi, *wo, *wx, *wdt;
    cudaGetSymbolAddress((void**)&xz,    g_xz);
    cudaGetSymbolAddress((void**)&xc,    g_xc);
    cudaGetSymbolAddress((void**)&xcs,   g_xcs);
    cudaGetSymbolAddress((void**)&xpart, g_xpart);
    cudaGetSymbolAddress((void**)&xdbl,  g_xdbl);
    cudaGetSymbolAddress((void**)&dtA,   g_dtA);
    cudaGetSymbolAddress((void**)&delta, g_delta);
    cudaGetSymbolAddress((void**)&ys,    g_ys);
    cudaGetSymbolAddress((void**)&xs,    g_xs);
    cudaGetSymbolAddress((void**)&wi,    g_wi);
    cudaGetSymbolAddress((void**)&wo,    g_wo);
    cudaGetSymbolAddress((void**)&wx,    g_wx);
    cudaGetSymbolAddress((void**)&wdt,   g_wdt);
    cudaGetSymbolAddress((void**)&Sarr,  g_S);
    cudaGetSymbolAddress((void**)&Parr,  g_P);
    cudaGetSymbolAddress((void**)&Hc,    g_Hc);

    const int SMEM_SZ = 6 * 16384;   // 96 KB -> 2 CTAs/SM
    static bool attr_set = false;
    if (!attr_set) {
        cudaFuncSetAttribute(hgemm<0>, cudaFuncAttributeMaxDynamicSharedMemorySize, SMEM_SZ);
        cudaFuncSetAttribute(hgemm<1>, cudaFuncAttributeMaxDynamicSharedMemorySize, SMEM_SZ);
        attr_set = true;
    }

    // launch 0-2: splits
    split_kernel<1><<<(BL * 1024 / 4 + 255) / 256, 256>>>(x, xs, 1024, BL * 1024 / 4, BL);
    split_kernel<0><<<(4096 * 1024 / 4 + 255) / 256, 256>>>(in_proj_w, wi, 1024, 4096 * 1024 / 4, 4096);
    split_rest<<<(N4_WO + N4_WX + N4_WDT + 255) / 256, 256>>>(
        out_proj, x_proj_w, dt_proj_w, wo, wx, wdt);

    // launch 3 (ncu -s 5 target): xz = x @ in_proj_w.T  (M=2048,N=4096,K'=3072)
    hgemm<0><<<dim3(32, 16, 1), 512, SMEM_SZ>>>(
        xs, wi, xz, 3072, 3072, 4096, 48, 0, nullptr);

    // launch 4: conv + silu (+ act-split)
    conv_silu_kernel<<<(BL * D_INNER + 255) / 256, 256>>>(xz, conv_w, conv_b, xc, xcs);

    // launch 5-6: x_dbl = xc @ x_proj_w.T (split-K=8) + reduce
    hgemm<0><<<dim3(1, 16, KS), 512, SMEM_SZ>>>(
        xcs, wx, xpart, 6144, 6144, 128, 6144 / KS / 64, (long)BL * 128, nullptr);
    reduce_split<<<(BL * 128 / 4 + 255) / 256, 256>>>(xpart, xdbl, dtA);

    // launch 7: delta = softplus(dt @ dt_proj_w.T + b)
    hgemm<1><<<dim3(16, 16, 1), 512, SMEM_SZ>>>(
        dtA, wdt, delta, 192, 192, 2048, 3, 0, dt_proj_b);

    // launch 8-10: chunked selective scan
    scan_pass_a<<<BB * NCH * D_INNER * D_STATE / 256, 256>>>(
        delta, xdbl, xc, A_log, Sarr, Parr);
    scan_pass_b<<<BB * D_INNER * D_STATE / 256, 256>>>(Sarr, Parr, Hc);
    scan_pass_c<<<BB * NCH * D_INNER * D_STATE / 256, 256>>>(
        delta, xdbl, xc, xz, A_log, Dv, Hc, ys);

    // launch 11: out = y @ out_proj_w.T
    hgemm<0><<<dim3(8, 16, 1), 512, SMEM_SZ>>>(
        ys, wo, out, 6144, 6144, 1024, 96, 0, nullptr);
}

// round 9
// speedup vs baseline: 2.6076x; 1.1358x over previous
#include <cuda_runtime.h>
#include <cuda_bf16.h>
#include <math.h>
#include <stdint.h>

// Problem constants
#define D_MODEL 1024
#define D_INNER 2048
#define D_STATE 16
#define DT_RANK 64
#define D_CONV  4
#define BB      2
#define LL      1024
#define BL      (BB * LL)                 // 2048 rows
#define KS      8                         // split-K for x_proj
#define NCH     8                         // scan chunks
#define CHL     (LL / NCH)                // 128 steps per chunk

// ---------------------------------------------------------------------------
// Device scratch. 3-segment K-concat split (K' = 3K):
//   activations: [hi | lo | hi],  weights: [hi | hi | lo]
// ---------------------------------------------------------------------------
__device__ float          g_xz[BL * 4096];
__device__ float          g_xc[BL * 2048];
__device__ __nv_bfloat16  g_xcs[BL * 6144];
__device__ float          g_xpart[KS * BL * 128];
__device__ float          g_xdbl[BL * 128];
__device__ __nv_bfloat16  g_dtA[BL * 192];
__device__ float          g_delta[BL * 2048];
__device__ __nv_bfloat16  g_ys[BL * 6144];
__device__ __nv_bfloat16  g_xs[BL * 3072];
__device__ __nv_bfloat16  g_wi[4096 * 3072];
__device__ __nv_bfloat16  g_wo[1024 * 6144];
__device__ __nv_bfloat16  g_wx[128 * 6144];
__device__ __nv_bfloat16  g_wdt[2048 * 192];
// transposed [d][token] operands for the scan
__device__ float          g_dtT[D_INNER * BL];
__device__ float          g_xcT[D_INNER * BL];
__device__ float          g_zT[D_INNER * BL];
__device__ float          g_yT[D_INNER * BL];
// chunked-scan intermediates, index t = ((b*NCH+c)*D_INNER+d)*16+n
__device__ float          g_S[BB * NCH * D_INNER * D_STATE];
__device__ float          g_P[BB * NCH * D_INNER * D_STATE];
__device__ float          g_Hc[BB * NCH * D_INNER * D_STATE];
// out_proj split-K partials
__device__ float          g_opart[2 * BL * D_MODEL];

// ---------------------------------------------------------------------------
// helpers
// ---------------------------------------------------------------------------
__device__ __forceinline__ void cvt_pair(float x, float y,
                                         uint32_t& hi, uint32_t& lo) {
    asm("cvt.rn.bf16x2.f32 %0, %1, %2;" : "=r"(hi) : "f"(y), "f"(x));
    const float hx = __uint_as_float(hi << 16);
    const float hy = __uint_as_float(hi & 0xFFFF0000u);
    asm("cvt.rn.bf16x2.f32 %0, %1, %2;" : "=r"(lo) : "f"(y - hy), "f"(x - hx));
}

__device__ __forceinline__ void cp16(uint32_t s, const void* g) {
    asm volatile("cp.async.cg.shared.global [%0], [%1], 16;" :: "r"(s), "l"(g));
}
__device__ __forceinline__ void cp_commit() {
    asm volatile("cp.async.commit_group;");
}
__device__ __forceinline__ void cp_wait1() {
    asm volatile("cp.async.wait_group 1;" ::: "memory");
}

#define LDSM_X4(r0, r1, r2, r3, addr) \
    asm volatile("ldmatrix.sync.aligned.m8n8.x4.shared.b16 {%0,%1,%2,%3}, [%4];" \
                 : "=r"(r0), "=r"(r1), "=r"(r2), "=r"(r3) : "r"(addr))

__device__ __forceinline__ void mma_bf16(float (&c)[4],
                                         uint32_t a0, uint32_t a1,
                                         uint32_t a2, uint32_t a3,
                                         uint32_t b0, uint32_t b1) {
    asm volatile(
        "mma.sync.aligned.m16n8k16.row.col.f32.bf16.bf16.f32 "
        "{%0,%1,%2,%3},{%4,%5,%6,%7},{%8,%9},{%0,%1,%2,%3};"
        : "+f"(c[0]), "+f"(c[1]), "+f"(c[2]), "+f"(c[3])
        : "r"(a0), "r"(a1), "r"(a2), "r"(a3), "r"(b0), "r"(b1));
}

// ---------------------------------------------------------------------------
// bf16 HGEMM (pre-split operands), BM=BN=128, BK=64, 512 thr, 3-stage ring.
// ---------------------------------------------------------------------------
template<int EPI>
__global__ void __launch_bounds__(512, 2)
hgemm(const __nv_bfloat16* __restrict__ A, const __nv_bfloat16* __restrict__ W,
      float* __restrict__ C, int lda, int ldw, int ldc, int T,
      long czstride, const float* __restrict__ bias)
{
    constexpr int S = 3;
    extern __shared__ __align__(16) char smem[];
    const uint32_t smA0 = (uint32_t)__cvta_generic_to_shared(smem);
    const uint32_t smB0 = smA0 + S * 16384;

    const int tid  = threadIdx.x;
    const int wid  = tid >> 5;
    const int lane = tid & 31;
    const int wm   = wid >> 2;
    const int wn   = wid & 3;
    const int l16  = lane & 15;
    const int chal = lane >> 4;

    const long blockM = (long)blockIdx.y * 128;
    const long blockN = (long)blockIdx.x * 128;
    const int  koff   = blockIdx.z * T * 64;

    const __nv_bfloat16* Ab = A + blockM * lda + koff;
    const __nv_bfloat16* Wb = W + blockN * ldw + koff;

    const int crow = tid >> 3;
    const int ccc  = tid & 7;

    uint32_t aoff[2], asw[2], boff[2], bsw[2];
#pragma unroll
    for (int mi = 0; mi < 2; mi++) {
        const int r = wm * 32 + mi * 16 + l16;
        aoff[mi] = r * 128;
        asw[mi]  = r & 7;
    }
#pragma unroll
    for (int ni = 0; ni < 2; ni++) {
        const int r = wn * 32 + ni * 16 + l16;
        boff[ni] = r * 128;
        bsw[ni]  = r & 7;
    }

    float acc[2][4][4];
#pragma unroll
    for (int mi = 0; mi < 2; mi++)
#pragma unroll
        for (int n8 = 0; n8 < 4; n8++)
#pragma unroll
            for (int j = 0; j < 4; j++) acc[mi][n8][j] = 0.f;

    auto issue = [&](int s, int t) {
        const int k0 = t * 64;
        const uint32_t dA = smA0 + s * 16384;
        const uint32_t dB = smB0 + s * 16384;
#pragma unroll
        for (int p = 0; p < 2; p++) {
            const int row = crow + p * 64;
            const int scc = ccc ^ (row & 7);
            cp16(dA + row * 128 + scc * 16, Ab + (long)row * lda + k0 + ccc * 8);
            cp16(dB + row * 128 + scc * 16, Wb + (long)row * ldw + k0 + ccc * 8);
        }
    };

    issue(0, 0);
    cp_commit();
    issue(1, 1);
    cp_commit();

    for (int t = 0; t < T; t++) {
        cp_wait1();
        __syncthreads();
        const int nt = t + 2;
        if (nt < T) issue(nt % S, nt);
        cp_commit();

        const uint32_t sA = smA0 + (t % S) * 16384;
        const uint32_t sB = smB0 + (t % S) * 16384;
#pragma unroll
        for (int k16 = 0; k16 < 4; k16++) {
            const uint32_t ch = (uint32_t)(k16 * 2 + chal);
            uint32_t a[2][4], b[2][4];
#pragma unroll
            for (int mi = 0; mi < 2; mi++)
                LDSM_X4(a[mi][0], a[mi][1], a[mi][2], a[mi][3],
                        sA + aoff[mi] + ((ch ^ asw[mi]) << 4));
#pragma unroll
            for (int ni = 0; ni < 2; ni++)
                LDSM_X4(b[ni][0], b[ni][1], b[ni][2], b[ni][3],
                        sB + boff[ni] + ((ch ^ bsw[ni]) << 4));
#pragma unroll
            for (int mi = 0; mi < 2; mi++)
#pragma unroll
                for (int n8 = 0; n8 < 4; n8++) {
                    const int np = n8 >> 1;
                    const uint32_t b0 = (n8 & 1) ? b[np][1] : b[np][0];
                    const uint32_t b1 = (n8 & 1) ? b[np][3] : b[np][2];
                    mma_bf16(acc[mi][n8],
                             a[mi][0], a[mi][1], a[mi][2], a[mi][3], b0, b1);
                }
        }
    }

    float* Cb = C + (long)blockIdx.z * czstride;
    const int er = lane >> 2;
    const int ec = (lane & 3) * 2;
#pragma unroll
    for (int mi = 0; mi < 2; mi++) {
#pragma unroll
        for (int n8 = 0; n8 < 4; n8++) {
            const long row = blockM + wm * 32 + mi * 16 + er;
            const int  col = (int)blockN + wn * 32 + n8 * 8 + ec;
            float v0 = acc[mi][n8][0], v1 = acc[mi][n8][1];
            float v2 = acc[mi][n8][2], v3 = acc[mi][n8][3];
            if (EPI == 1) {
                const float b0 = bias[col], b1 = bias[col + 1];
                v0 += b0; v1 += b1; v2 += b0; v3 += b1;
                v0 = (v0 > 20.f) ? v0 : log1pf(expf(v0));
                v1 = (v1 > 20.f) ? v1 : log1pf(expf(v1));
                v2 = (v2 > 20.f) ? v2 : log1pf(expf(v2));
                v3 = (v3 > 20.f) ? v3 : log1pf(expf(v3));
            }
            *(float2*)&Cb[row * ldc + col]       = make_float2(v0, v1);
            *(float2*)&Cb[(row + 8) * ldc + col] = make_float2(v2, v3);
        }
    }
}

// ---------------------------------------------------------------------------
// f32 -> bf16 3-segment split
// ---------------------------------------------------------------------------
__device__ __forceinline__ void split_body(const float* __restrict__ in,
                                           __nv_bfloat16* __restrict__ out,
                                           int K, int li, int inRows, int act)
{
    const int e   = li * 4;
    const int row = e / K;
    const int k   = e - row * K;
    float4 v = make_float4(0.f, 0.f, 0.f, 0.f);
    if (row < inRows) v = *(const float4*)(in + (long)row * K + k);
    uint32_t h01, l01, h23, l23;
    cvt_pair(v.x, v.y, h01, l01);
    cvt_pair(v.z, v.w, h23, l23);
    __nv_bfloat16* o = out + (long)row * 3 * K + k;
    const uint2 hv = make_uint2(h01, h23);
    const uint2 lv = make_uint2(l01, l23);
    if (act) {
        *(uint2*)o           = hv;
        *(uint2*)(o + K)     = lv;
        *(uint2*)(o + 2 * K) = hv;
    } else {
        *(uint2*)o           = hv;
        *(uint2*)(o + K)     = hv;
        *(uint2*)(o + 2 * K) = lv;
    }
}

template<int ACT>
__global__ void split_kernel(const float* __restrict__ in,
                             __nv_bfloat16* __restrict__ out,
                             int K, int n4, int inRows)
{
    const int i = blockIdx.x * 256 + threadIdx.x;
    if (i >= n4) return;
    split_body(in, out, K, i, inRows, ACT);
}

#define N4_WO (1024 * 2048 / 4)
#define N4_WX (128 * 2048 / 4)
#define N4_WDT (2048 * 64 / 4)
__global__ void split_rest(const float* __restrict__ wo_in,
                           const float* __restrict__ wx_in,
                           const float* __restrict__ wdt_in,
                           __nv_bfloat16* __restrict__ wo,
                           __nv_bfloat16* __restrict__ wx,
                           __nv_bfloat16* __restrict__ wdt)
{
    const int i = blockIdx.x * 256 + threadIdx.x;
    if (i < N4_WO) {
        split_body(wo_in, wo, 2048, i, 1024, 0);
    } else if (i < N4_WO + N4_WX) {
        split_body(wx_in, wx, 2048, i - N4_WO, 96, 0);
    } else if (i < N4_WO + N4_WX + N4_WDT) {
        split_body(wdt_in, wdt, 64, i - N4_WO - N4_WX, 2048, 0);
    }
}

// ---------------------------------------------------------------------------
// Split-K reduce for x_proj partials + dt-row act-split
// ---------------------------------------------------------------------------
__global__ void reduce_split(const float* __restrict__ p,
                             float* __restrict__ xdbl,
                             __nv_bfloat16* __restrict__ dtA)
{
    const int n4 = BL * 128 / 4;
    const int i = blockIdx.x * 256 + threadIdx.x;
    if (i >= n4) return;
    float4 a = ((const float4*)p)[i];
#pragma unroll
    for (int s = 1; s < KS; s++) {
        const float4 b = ((const float4*)p)[(long)s * n4 + i];
        a.x += b.x; a.y += b.y; a.z += b.z; a.w += b.w;
    }
    ((float4*)xdbl)[i] = a;
    const int e = i * 4;
    const int col = e & 127;
    if (col < 64) {
        const int row = e >> 7;
        uint32_t h01, l01, h23, l23;
        cvt_pair(a.x, a.y, h01, l01);
        cvt_pair(a.z, a.w, h23, l23);
        __nv_bfloat16* o = dtA + (long)row * 192 + col;
        const uint2 hv = make_uint2(h01, h23);
        *(uint2*)o         = hv;
        *(uint2*)(o + 64)  = make_uint2(l01, l23);
        *(uint2*)(o + 128) = hv;
    }
}

// ---------------------------------------------------------------------------
// Depthwise causal conv (k=4) + bias + SiLU; writes f32 + act-split bf16
// ---------------------------------------------------------------------------
__global__ void conv_silu_kernel(const float* __restrict__ xz,
                                 const float* __restrict__ cw,
                                 const float* __restrict__ cb,
                                 float* __restrict__ xc,
                                 __nv_bfloat16* __restrict__ xcs)
{
    const int idx = blockIdx.x * blockDim.x + threadIdx.x;
    if (idx >= BL * D_INNER) return;
    const int d = idx & (D_INNER - 1);
    const int r = idx >> 11;
    const int l = r & (LL - 1);
    const int b = r >> 10;

    float acc = cb[d];
#pragma unroll
    for (int i = 0; i < D_CONV; i++) {
        const int ll = l - (D_CONV - 1) + i;
        if (ll >= 0)
            acc = fmaf(xz[((long)(b * LL + ll)) * 4096 + d],
                       cw[d * D_CONV + i], acc);
    }
    const float s = acc / (1.f + expf(-acc));
    xc[idx] = s;
    const __nv_bfloat16 h = __float2bfloat16(s);
    __nv_bfloat16* o = xcs + (long)r * 6144 + d;
    o[0]    = h;
    o[2048] = __float2bfloat16(s - __bfloat162float(h));
    o[4096] = h;
}

// ---------------------------------------------------------------------------
// Tiled transpose of the three scan operands into [d][token] layout.
// blockIdx.z selects source: 0 delta (ld 2048), 1 xc (ld 2048),
// 2 z = xz[:, 2048:] (ld 4096). 32x32 tiles, block (32,8).
// ---------------------------------------------------------------------------
__global__ void transpose3(const float* __restrict__ delta,
                           const float* __restrict__ xc,
                           const float* __restrict__ xz,
                           float* __restrict__ dtT,
                           float* __restrict__ xcT,
                           float* __restrict__ zT)
{
    __shared__ float tile[32][33];
    const int sel = blockIdx.z;
    const float* src = (sel == 0) ? delta : (sel == 1) ? xc : xz;
    const int ldin   = (sel == 2) ? 4096 : 2048;
    const int coff   = (sel == 2) ? 2048 : 0;
    float* dst = (sel == 0) ? dtT : (sel == 1) ? xcT : zT;

    const int r0 = blockIdx.y * 32;   // token rows
    const int c0 = blockIdx.x * 32;   // d cols
#pragma unroll
    for (int i = threadIdx.y; i < 32; i += 8)
        tile[i][threadIdx.x] = src[(long)(r0 + i) * ldin + coff + c0 + threadIdx.x];
    __syncthreads();
#pragma unroll
    for (int i = threadIdx.y; i < 32; i += 8)
        dst[(long)(c0 + i) * BL + r0 + threadIdx.x] = tile[threadIdx.x][i];
}

// ---------------------------------------------------------------------------
// yT [d][token] -> ys [token][6144] act-split (tiled transpose + bf16 split)
// ---------------------------------------------------------------------------
__global__ void ysplit(const float* __restrict__ yT,
                       __nv_bfloat16* __restrict__ ys)
{
    __shared__ float tile[32][33];
    const int d0 = blockIdx.x * 32;
    const int r0 = blockIdx.y * 32;
#pragma unroll
    for (int i = threadIdx.y; i < 32; i += 8)
        tile[i][threadIdx.x] = yT[(long)(d0 + i) * BL + r0 + threadIdx.x];
    __syncthreads();
#pragma unroll
    for (int i = threadIdx.y; i < 32; i += 8) {
        const float v = tile[threadIdx.x][i];
        const int row = r0 + i;
        const int d   = d0 + threadIdx.x;
        const __nv_bfloat16 hh = __float2bfloat16(v);
        __nv_bfloat16* o = ys + (long)row * 6144 + d;
        o[0]    = hh;
        o[2048] = __float2bfloat16(v - __bfloat162float(hh));
        o[4096] = hh;
    }
}

// ---------------------------------------------------------------------------
// Chunked selective scan over transposed operands.
// t = ((b*NCH + c)*D_INNER + d)*16 + n
// ---------------------------------------------------------------------------
__global__ void scan_pass_a(const float* __restrict__ dtT,
                            const float* __restrict__ xcT,
                            const float* __restrict__ xdbl,
                            const float* __restrict__ A_log,
                            float* __restrict__ Sarr,
                            float* __restrict__ Parr)
{
    const int t = blockIdx.x * 256 + threadIdx.x;
    const int n = t & 15;
    const int g = t >> 4;
    const int d = g & (D_INNER - 1);
    const int c = (g >> 11) & (NCH - 1);
    const int b = g >> 14;

    const float Aval = -__expf(A_log[d * D_STATE + n]);
    const long base = ((long)d << 11) + (b << 10) + c * CHL;
    const float4* dp4 = (const float4*)(dtT + base);
    const float4* xp4 = (const float4*)(xcT + base);
    const float* xdp  = xdbl + ((long)b * LL + c * CHL) * 128 + 64 + n;

    float h = 0.f, Pr = 1.f;
#pragma unroll 4
    for (int q = 0; q < CHL / 4; q++) {
        const float4 dl4 = dp4[q];
        const float4 xc4 = xp4[q];
#pragma unroll
        for (int j = 0; j < 4; j++) {
            const float dl  = (j == 0) ? dl4.x : (j == 1) ? dl4.y : (j == 2) ? dl4.z : dl4.w;
            const float xcv = (j == 0) ? xc4.x : (j == 1) ? xc4.y : (j == 2) ? xc4.z : xc4.w;
            const float Bv  = xdp[(q * 4 + j) * 128];
            const float a   = __expf(dl * Aval);
            Pr *= a;
            h = fmaf(a, h, dl * Bv * xcv);
        }
    }
    Sarr[t] = h;
    Parr[t] = Pr;
}

__global__ void scan_pass_b(const float* __restrict__ Sarr,
                            const float* __restrict__ Parr,
                            float* __restrict__ Hc)
{
    const int t = blockIdx.x * 256 + threadIdx.x;
    const int n = t & 15;
    const int d = (t >> 4) & (D_INNER - 1);
    const int b = t >> 15;
    float H = 0.f;
#pragma unroll
    for (int c = 0; c < NCH; c++) {
        const long idx = ((long)((b * NCH + c) * D_INNER + d) << 4) + n;
        Hc[idx] = H;
        H = fmaf(Parr[idx], H, Sarr[idx]);
    }
}

__global__ void scan_pass_c(const float* __restrict__ dtT,
                            const float* __restrict__ xcT,
                            const float* __restrict__ zT,
                            const float* __restrict__ xdbl,
                            const float* __restrict__ A_log,
                            const float* __restrict__ Dv,
                            const float* __restrict__ Hc,
                            float* __restrict__ yT)
{
    const int t = blockIdx.x * 256 + threadIdx.x;
    const int n = t & 15;
    const int g = t >> 4;
    const int d = g & (D_INNER - 1);
    const int c = (g >> 11) & (NCH - 1);
    const int b = g >> 14;

    const float Aval = -__expf(A_log[d * D_STATE + n]);
    const float Dd   = Dv[d];

    const long base = ((long)d << 11) + (b << 10) + c * CHL;
    const float4* dp4 = (const float4*)(dtT + base);
    const float4* xp4 = (const float4*)(xcT + base);
    const float4* zp4 = (const float4*)(zT + base);
    const float* xdp  = xdbl + ((long)b * LL + c * CHL) * 128 + 64 + n;
    float* yp = yT + base;

    float h = Hc[t];
    for (int q = 0; q < CHL / 4; q++) {
        const float4 dl4 = dp4[q];
        const float4 xc4 = xp4[q];
        const float4 zv4 = zp4[q];
#pragma unroll
        for (int j = 0; j < 4; j++) {
            const float dl  = (j == 0) ? dl4.x : (j == 1) ? dl4.y : (j == 2) ? dl4.z : dl4.w;
            const float xcv = (j == 0) ? xc4.x : (j == 1) ? xc4.y : (j == 2) ? xc4.z : xc4.w;
            const float zv  = (j == 0) ? zv4.x : (j == 1) ? zv4.y : (j == 2) ? zv4.z : zv4.w;
            const float Bv  = xdp[(q * 4 + j) * 128];
            const float Cv  = xdp[(q * 4 + j) * 128 + 16];

            const float a = __expf(dl * Aval);
            h = fmaf(a, h, dl * Bv * xcv);

            float p = h * Cv;
            p += __shfl_xor_sync(0xffffffffu, p, 8);
            p += __shfl_xor_sync(0xffffffffu, p, 4);
            p += __shfl_xor_sync(0xffffffffu, p, 2);
            p += __shfl_xor_sync(0xffffffffu, p, 1);

            if (n == 0) {
                const float sig = 1.f / (1.f + __expf(-zv));
                yp[q * 4 + j] = (p + xcv * Dd) * (zv * sig);
            }
        }
    }
}

// ---------------------------------------------------------------------------
// out_proj split-K=2 final reduce
// ---------------------------------------------------------------------------
__global__ void reduce_out(const float* __restrict__ p, float* __restrict__ o)
{
    const int n4 = BL * D_MODEL / 4;
    const int i = blockIdx.x * 256 + threadIdx.x;
    if (i >= n4) return;
    const float4 a = ((const float4*)p)[i];
    const float4 b = ((const float4*)p)[n4 + i];
    ((float4*)o)[i] = make_float4(a.x + b.x, a.y + b.y, a.z + b.z, a.w + b.w);
}

// ---------------------------------------------------------------------------
// Launch
// ---------------------------------------------------------------------------
extern "C" void kernel_launch(void* const* d_in, const int* in_sizes, int n_in,
                              void* d_out, int out_size)
{
    const float* x         = (const float*)d_in[0];
    const float* in_proj_w = (const float*)d_in[1];
    const float* conv_w    = (const float*)d_in[2];
    const float* conv_b    = (const float*)d_in[3];
    const float* x_proj_w  = (const float*)d_in[4];
    const float* dt_proj_w = (const float*)d_in[5];
    const float* dt_proj_b = (const float*)d_in[6];
    const float* A_log     = (const float*)d_in[7];
    const float* Dv        = (const float*)d_in[8];
    const float* out_proj  = (const float*)d_in[9];
    float* out = (float*)d_out;

    float *xz, *xc, *xpart, *xdbl, *delta, *dtT, *xcT, *zT, *yT;
    float *Sarr, *Parr, *Hc, *opart;
    __nv_bfloat16 *xcs, *dtA, *ys, *xs, *wi, *wo, *wx, *wdt;
    cudaGetSymbolAddress((void**)&xz,    g_xz);
    cudaGetSymbolAddress((void**)&xc,    g_xc);
    cudaGetSymbolAddress((void**)&xcs,   g_xcs);
    cudaGetSymbolAddress((void**)&xpart, g_xpart);
    cudaGetSymbolAddress((void**)&xdbl,  g_xdbl);
    cudaGetSymbolAddress((void**)&dtA,   g_dtA);
    cudaGetSymbolAddress((void**)&delta, g_delta);
    cudaGetSymbolAddress((void**)&ys,    g_ys);
    cudaGetSymbolAddress((void**)&xs,    g_xs);
    cudaGetSymbolAddress((void**)&wi,    g_wi);
    cudaGetSymbolAddress((void**)&wo,    g_wo);
    cudaGetSymbolAddress((void**)&wx,    g_wx);
    cudaGetSymbolAddress((void**)&wdt,   g_wdt);
    cudaGetSymbolAddress((void**)&dtT,   g_dtT);
    cudaGetSymbolAddress((void**)&xcT,   g_xcT);
    cudaGetSymbolAddress((void**)&zT,    g_zT);
    cudaGetSymbolAddress((void**)&yT,    g_yT);
    cudaGetSymbolAddress((void**)&Sarr,  g_S);
    cudaGetSymbolAddress((void**)&Parr,  g_P);
    cudaGetSymbolAddress((void**)&Hc,    g_Hc);
    cudaGetSymbolAddress((void**)&opart, g_opart);

    const int SMEM_SZ = 6 * 16384;   // 96 KB -> 2 CTAs/SM
    static bool attr_set = false;
    if (!attr_set) {
        cudaFuncSetAttribute(hgemm<0>, cudaFuncAttributeMaxDynamicSharedMemorySize, SMEM_SZ);
        cudaFuncSetAttribute(hgemm<1>, cudaFuncAttributeMaxDynamicSharedMemorySize, SMEM_SZ);
        attr_set = true;
    }

    // launch 0-2: splits
    split_kernel<1><<<(BL * 1024 / 4 + 255) / 256, 256>>>(x, xs, 1024, BL * 1024 / 4, BL);
    split_kernel<0><<<(4096 * 1024 / 4 + 255) / 256, 256>>>(in_proj_w, wi, 1024, 4096 * 1024 / 4, 4096);
    split_rest<<<(N4_WO + N4_WX + N4_WDT + 255) / 256, 256>>>(
        out_proj, x_proj_w, dt_proj_w, wo, wx, wdt);

    // launch 3 (profiled): xz = x @ in_proj_w.T  (M=2048, N=4096, K'=3072)
    hgemm<0><<<dim3(32, 16, 1), 512, SMEM_SZ>>>(
        xs, wi, xz, 3072, 3072, 4096, 48, 0, nullptr);

    // launch 4: conv + silu (+ act-split)
    conv_silu_kernel<<<(BL * D_INNER + 255) / 256, 256>>>(xz, conv_w, conv_b, xc, xcs);

    // launch 5-6: x_dbl = xc @ x_proj_w.T (split-K=8) + reduce
    hgemm<0><<<dim3(1, 16, KS), 512, SMEM_SZ>>>(
        xcs, wx, xpart, 6144, 6144, 128, 6144 / KS / 64, (long)BL * 128, nullptr);
    reduce_split<<<(BL * 128 / 4 + 255) / 256, 256>>>(xpart, xdbl, dtA);

    // launch 7: delta = softplus(dt @ dt_proj_w.T + b)
    hgemm<1><<<dim3(16, 16, 1), 512, SMEM_SZ>>>(
        dtA, wdt, delta, 192, 192, 2048, 3, 0, dt_proj_b);

    // launch 8: transpose delta/xc/z into [d][token]
    transpose3<<<dim3(64, 64, 3), dim3(32, 8)>>>(delta, xc, xz, dtT, xcT, zT);

    // launch 9-11: chunked selective scan (coalesced operands)
    scan_pass_a<<<BB * NCH * D_INNER * D_STATE / 256, 256>>>(
        dtT, xcT, xdbl, A_log, Sarr, Parr);
    scan_pass_b<<<BB * D_INNER * D_STATE / 256, 256>>>(Sarr, Parr, Hc);
    scan_pass_c<<<BB * NCH * D_INNER * D_STATE / 256, 256>>>(
        dtT, xcT, zT, xdbl, A_log, Dv, Hc, yT);

    // launch 12: yT -> ys (act-split, coalesced)
    ysplit<<<dim3(64, 64), dim3(32, 8)>>>(yT, ys);

    // launch 13-14: out = y @ out_proj_w.T (split-K=2) + reduce
    hgemm<0><<<dim3(8, 16, 2), 512, SMEM_SZ>>>(
        ys, wo, opart, 6144, 6144, 1024, 48, (long)BL * D_MODEL, nullptr);
    reduce_out<<<(BL * D_MODEL / 4 + 255) / 256, 256>>>(opart, out);
}

// round 10
// speedup vs baseline: 2.7015x; 1.0360x over previous
#include <cuda_runtime.h>
#include <cuda_bf16.h>
#include <math.h>
#include <stdint.h>

// Problem constants
#define D_MODEL 1024
#define D_INNER 2048
#define D_STATE 16
#define DT_RANK 64
#define D_CONV  4
#define BB      2
#define LL      1024
#define BL      (BB * LL)                 // 2048 tokens
#define KS      16                        // split-K for x_proj
#define NCH     8                         // scan chunks
#define CHL     (LL / NCH)                // 128 steps per chunk

// ---------------------------------------------------------------------------
// Device scratch. 3-segment K-concat split (K' = 3K):
//   act-style: [hi | lo | hi], wt-style: [hi | hi | lo]
// (pairing either way yields hh + hl + lh = 3-term compensated product)
// Transposed dataflow: xzT/xcT/deltaT/yT are [channel][token].
// ---------------------------------------------------------------------------
__device__ float          g_xzT[4096 * BL];         // in_proj out, transposed
__device__ float          g_xcT[D_INNER * BL];      // conv out, transposed
__device__ __nv_bfloat16  g_xcs[BL * 6144];         // xc act-split (for x_proj)
__device__ float          g_xpart[KS * BL * 128];   // x_proj split-K partials
__device__ float          g_xdbl[BL * 128];         // x_proj out [token][128]
__device__ __nv_bfloat16  g_dtA[BL * 192];          // dt rows act-split
__device__ float          g_deltaT[D_INNER * BL];   // softplus'd delta, transposed
__device__ float          g_yT[D_INNER * BL];       // scan out, transposed
__device__ __nv_bfloat16  g_ys[BL * 6144];          // y act-split (for out_proj)
__device__ __nv_bfloat16  g_xs[BL * 3072];          // x act-split
__device__ __nv_bfloat16  g_wi[4096 * 3072];        // in_proj_w wt-split
__device__ __nv_bfloat16  g_wo[1024 * 6144];        // out_proj_w wt-split
__device__ __nv_bfloat16  g_wx[128 * 6144];         // x_proj_w wt-split (pad 128)
__device__ __nv_bfloat16  g_wdt[2048 * 192];        // dt_proj_w wt-split
// chunked-scan intermediates, t = ((b*NCH+c)*D_INNER+d)*16+n
__device__ float          g_S[BB * NCH * D_INNER * D_STATE];
__device__ float          g_P[BB * NCH * D_INNER * D_STATE];
__device__ float          g_Hc[BB * NCH * D_INNER * D_STATE];
// out_proj split-K partials
__device__ float          g_opart[2 * BL * D_MODEL];

// ---------------------------------------------------------------------------
// helpers
// ---------------------------------------------------------------------------
__device__ __forceinline__ void cvt_pair(float x, float y,
                                         uint32_t& hi, uint32_t& lo) {
    asm("cvt.rn.bf16x2.f32 %0, %1, %2;" : "=r"(hi) : "f"(y), "f"(x));
    const float hx = __uint_as_float(hi << 16);
    const float hy = __uint_as_float(hi & 0xFFFF0000u);
    asm("cvt.rn.bf16x2.f32 %0, %1, %2;" : "=r"(lo) : "f"(y - hy), "f"(x - hx));
}

__device__ __forceinline__ void cp16(uint32_t s, const void* g) {
    asm volatile("cp.async.cg.shared.global [%0], [%1], 16;" :: "r"(s), "l"(g));
}
__device__ __forceinline__ void cp_commit() {
    asm volatile("cp.async.commit_group;");
}
__device__ __forceinline__ void cp_wait1() {
    asm volatile("cp.async.wait_group 1;" ::: "memory");
}

#define LDSM_X4(r0, r1, r2, r3, addr) \
    asm volatile("ldmatrix.sync.aligned.m8n8.x4.shared.b16 {%0,%1,%2,%3}, [%4];" \
                 : "=r"(r0), "=r"(r1), "=r"(r2), "=r"(r3) : "r"(addr))

__device__ __forceinline__ void mma_bf16(float (&c)[4],
                                         uint32_t a0, uint32_t a1,
                                         uint32_t a2, uint32_t a3,
                                         uint32_t b0, uint32_t b1) {
    asm volatile(
        "mma.sync.aligned.m16n8k16.row.col.f32.bf16.bf16.f32 "
        "{%0,%1,%2,%3},{%4,%5,%6,%7},{%8,%9},{%0,%1,%2,%3};"
        : "+f"(c[0]), "+f"(c[1]), "+f"(c[2]), "+f"(c[3])
        : "r"(a0), "r"(a1), "r"(a2), "r"(a3), "r"(b0), "r"(b1));
}

// ---------------------------------------------------------------------------
// bf16 HGEMM (pre-split operands), BM=BN=128, BK=64, 512 thr, 3-stage ring.
// EPI==1: +bias[col], softplus.  EPI==2: +bias[row], softplus (swapped GEMMs).
// Split-K via blockIdx.z. Requires M%128==0, N%128==0, K'%64==0/split, T>=2.
// ---------------------------------------------------------------------------
template<int EPI>
__global__ void __launch_bounds__(512, 2)
hgemm(const __nv_bfloat16* __restrict__ A, const __nv_bfloat16* __restrict__ W,
      float* __restrict__ C, int lda, int ldw, int ldc, int T,
      long czstride, const float* __restrict__ bias)
{
    constexpr int S = 3;
    extern __shared__ __align__(16) char smem[];
    const uint32_t smA0 = (uint32_t)__cvta_generic_to_shared(smem);
    const uint32_t smB0 = smA0 + S * 16384;

    const int tid  = threadIdx.x;
    const int wid  = tid >> 5;
    const int lane = tid & 31;
    const int wm   = wid >> 2;
    const int wn   = wid & 3;
    const int l16  = lane & 15;
    const int chal = lane >> 4;

    const long blockM = (long)blockIdx.y * 128;
    const long blockN = (long)blockIdx.x * 128;
    const int  koff   = blockIdx.z * T * 64;

    const __nv_bfloat16* Ab = A + blockM * lda + koff;
    const __nv_bfloat16* Wb = W + blockN * ldw + koff;

    const int crow = tid >> 3;
    const int ccc  = tid & 7;

    uint32_t aoff[2], asw[2], boff[2], bsw[2];
#pragma unroll
    for (int mi = 0; mi < 2; mi++) {
        const int r = wm * 32 + mi * 16 + l16;
        aoff[mi] = r * 128;
        asw[mi]  = r & 7;
    }
#pragma unroll
    for (int ni = 0; ni < 2; ni++) {
        const int r = wn * 32 + ni * 16 + l16;
        boff[ni] = r * 128;
        bsw[ni]  = r & 7;
    }

    float acc[2][4][4];
#pragma unroll
    for (int mi = 0; mi < 2; mi++)
#pragma unroll
        for (int n8 = 0; n8 < 4; n8++)
#pragma unroll
            for (int j = 0; j < 4; j++) acc[mi][n8][j] = 0.f;

    auto issue = [&](int s, int t) {
        const int k0 = t * 64;
        const uint32_t dA = smA0 + s * 16384;
        const uint32_t dB = smB0 + s * 16384;
#pragma unroll
        for (int p = 0; p < 2; p++) {
            const int row = crow + p * 64;
            const int scc = ccc ^ (row & 7);
            cp16(dA + row * 128 + scc * 16, Ab + (long)row * lda + k0 + ccc * 8);
            cp16(dB + row * 128 + scc * 16, Wb + (long)row * ldw + k0 + ccc * 8);
        }
    };

    issue(0, 0);
    cp_commit();
    issue(1, 1);
    cp_commit();

    for (int t = 0; t < T; t++) {
        cp_wait1();
        __syncthreads();
        const int nt = t + 2;
        if (nt < T) issue(nt % S, nt);
        cp_commit();

        const uint32_t sA = smA0 + (t % S) * 16384;
        const uint32_t sB = smB0 + (t % S) * 16384;
#pragma unroll
        for (int k16 = 0; k16 < 4; k16++) {
            const uint32_t ch = (uint32_t)(k16 * 2 + chal);
            uint32_t a[2][4], b[2][4];
#pragma unroll
            for (int mi = 0; mi < 2; mi++)
                LDSM_X4(a[mi][0], a[mi][1], a[mi][2], a[mi][3],
                        sA + aoff[mi] + ((ch ^ asw[mi]) << 4));
#pragma unroll
            for (int ni = 0; ni < 2; ni++)
                LDSM_X4(b[ni][0], b[ni][1], b[ni][2], b[ni][3],
                        sB + boff[ni] + ((ch ^ bsw[ni]) << 4));
#pragma unroll
            for (int mi = 0; mi < 2; mi++)
#pragma unroll
                for (int n8 = 0; n8 < 4; n8++) {
                    const int np = n8 >> 1;
                    const uint32_t b0 = (n8 & 1) ? b[np][1] : b[np][0];
                    const uint32_t b1 = (n8 & 1) ? b[np][3] : b[np][2];
                    mma_bf16(acc[mi][n8],
                             a[mi][0], a[mi][1], a[mi][2], a[mi][3], b0, b1);
                }
        }
    }

    float* Cb = C + (long)blockIdx.z * czstride;
    const int er = lane >> 2;
    const int ec = (lane & 3) * 2;
#pragma unroll
    for (int mi = 0; mi < 2; mi++) {
#pragma unroll
        for (int n8 = 0; n8 < 4; n8++) {
            const long row = blockM + wm * 32 + mi * 16 + er;
            const int  col = (int)blockN + wn * 32 + n8 * 8 + ec;
            float v0 = acc[mi][n8][0], v1 = acc[mi][n8][1];
            float v2 = acc[mi][n8][2], v3 = acc[mi][n8][3];
            if (EPI == 1) {
                const float b0 = bias[col], b1 = bias[col + 1];
                v0 += b0; v1 += b1; v2 += b0; v3 += b1;
                v0 = (v0 > 20.f) ? v0 : log1pf(expf(v0));
                v1 = (v1 > 20.f) ? v1 : log1pf(expf(v1));
                v2 = (v2 > 20.f) ? v2 : log1pf(expf(v2));
                v3 = (v3 > 20.f) ? v3 : log1pf(expf(v3));
            } else if (EPI == 2) {
                const float br = bias[row], br8 = bias[row + 8];
                v0 += br; v1 += br; v2 += br8; v3 += br8;
                v0 = (v0 > 20.f) ? v0 : log1pf(expf(v0));
                v1 = (v1 > 20.f) ? v1 : log1pf(expf(v1));
                v2 = (v2 > 20.f) ? v2 : log1pf(expf(v2));
                v3 = (v3 > 20.f) ? v3 : log1pf(expf(v3));
            }
            *(float2*)&Cb[row * ldc + col]       = make_float2(v0, v1);
            *(float2*)&Cb[(row + 8) * ldc + col] = make_float2(v2, v3);
        }
    }
}

// ---------------------------------------------------------------------------
// f32 -> bf16 3-segment split (row-major sources)
// ---------------------------------------------------------------------------
__device__ __forceinline__ void split_body(const float* __restrict__ in,
                                           __nv_bfloat16* __restrict__ out,
                                           int K, int li, int inRows, int act)
{
    const int e   = li * 4;
    const int row = e / K;
    const int k   = e - row * K;
    float4 v = make_float4(0.f, 0.f, 0.f, 0.f);
    if (row < inRows) v = *(const float4*)(in + (long)row * K + k);
    uint32_t h01, l01, h23, l23;
    cvt_pair(v.x, v.y, h01, l01);
    cvt_pair(v.z, v.w, h23, l23);
    __nv_bfloat16* o = out + (long)row * 3 * K + k;
    const uint2 hv = make_uint2(h01, h23);
    const uint2 lv = make_uint2(l01, l23);
    if (act) {
        *(uint2*)o           = hv;
        *(uint2*)(o + K)     = lv;
        *(uint2*)(o + 2 * K) = hv;
    } else {
        *(uint2*)o           = hv;
        *(uint2*)(o + K)     = hv;
        *(uint2*)(o + 2 * K) = lv;
    }
}

template<int ACT>
__global__ void split_kernel(const float* __restrict__ in,
                             __nv_bfloat16* __restrict__ out,
                             int K, int n4, int inRows)
{
    const int i = blockIdx.x * 256 + threadIdx.x;
    if (i >= n4) return;
    split_body(in, out, K, i, inRows, ACT);
}

#define N4_WO (1024 * 2048 / 4)
#define N4_WX (128 * 2048 / 4)
#define N4_WDT (2048 * 64 / 4)
__global__ void split_rest(const float* __restrict__ wo_in,
                           const float* __restrict__ wx_in,
                           const float* __restrict__ wdt_in,
                           __nv_bfloat16* __restrict__ wo,
                           __nv_bfloat16* __restrict__ wx,
                           __nv_bfloat16* __restrict__ wdt)
{
    const int i = blockIdx.x * 256 + threadIdx.x;
    if (i < N4_WO) {
        split_body(wo_in, wo, 2048, i, 1024, 0);
    } else if (i < N4_WO + N4_WX) {
        split_body(wx_in, wx, 2048, i - N4_WO, 96, 0);
    } else if (i < N4_WO + N4_WX + N4_WDT) {
        split_body(wdt_in, wdt, 64, i - N4_WO - N4_WX, 2048, 0);
    }
}

// ---------------------------------------------------------------------------
// Split-K reduce for x_proj partials + dt-row act-split
// ---------------------------------------------------------------------------
__global__ void reduce_split(const float* __restrict__ p,
                             float* __restrict__ xdbl,
                             __nv_bfloat16* __restrict__ dtA)
{
    const int n4 = BL * 128 / 4;
    const int i = blockIdx.x * 256 + threadIdx.x;
    if (i >= n4) return;
    float4 a = ((const float4*)p)[i];
#pragma unroll
    for (int s = 1; s < KS; s++) {
        const float4 b = ((const float4*)p)[(long)s * n4 + i];
        a.x += b.x; a.y += b.y; a.z += b.z; a.w += b.w;
    }
    ((float4*)xdbl)[i] = a;
    const int e = i * 4;
    const int col = e & 127;
    if (col < 64) {
        const int row = e >> 7;
        uint32_t h01, l01, h23, l23;
        cvt_pair(a.x, a.y, h01, l01);
        cvt_pair(a.z, a.w, h23, l23);
        __nv_bfloat16* o = dtA + (long)row * 192 + col;
        const uint2 hv = make_uint2(h01, h23);
        *(uint2*)o         = hv;
        *(uint2*)(o + 64)  = make_uint2(l01, l23);
        *(uint2*)(o + 128) = hv;
    }
}

// ---------------------------------------------------------------------------
// Depthwise causal conv (k=4) + bias + SiLU in transposed layout.
// Reads xzT[d][token] (coalesced), writes xcT[d][token] (coalesced).
// ---------------------------------------------------------------------------
__global__ void conv_silu_T(const float* __restrict__ xzT,
                            const float* __restrict__ cw,
                            const float* __restrict__ cb,
                            float* __restrict__ xcT)
{
    const int idx = blockIdx.x * 256 + threadIdx.x;
    if (idx >= D_INNER * BL) return;
    const int tt = idx & (BL - 1);     // global token
    const int d  = idx >> 11;
    const int l  = tt & (LL - 1);      // local position within batch

    const float* row = xzT + ((long)d << 11);
    float acc = cb[d];
#pragma unroll
    for (int i = 0; i < D_CONV; i++) {
        const int ll = l - (D_CONV - 1) + i;
        if (ll >= 0)
            acc = fmaf(row[tt - (D_CONV - 1) + i], cw[d * D_CONV + i], acc);
    }
    xcT[idx] = acc / (1.f + __expf(-acc));
}

// ---------------------------------------------------------------------------
// [d][token] f32 -> [token][6144] act-split bf16 (tiled transpose + split).
// Used for xcT->xcs and yT->ys.
// ---------------------------------------------------------------------------
__global__ void splitT(const float* __restrict__ src,
                       __nv_bfloat16* __restrict__ dst)
{
    __shared__ float tile[32][33];
    const int d0 = blockIdx.x * 32;
    const int r0 = blockIdx.y * 32;
#pragma unroll
    for (int i = threadIdx.y; i < 32; i += 8)
        tile[i][threadIdx.x] = src[(long)(d0 + i) * BL + r0 + threadIdx.x];
    __syncthreads();
#pragma unroll
    for (int i = threadIdx.y; i < 32; i += 8) {
        const float v = tile[threadIdx.x][i];
        const int row = r0 + i;
        const int d   = d0 + threadIdx.x;
        const __nv_bfloat16 hh = __float2bfloat16(v);
        __nv_bfloat16* o = dst + (long)row * 6144 + d;
        o[0]    = hh;
        o[2048] = __float2bfloat16(v - __bfloat162float(hh));
        o[4096] = hh;
    }
}

// ---------------------------------------------------------------------------
// Chunked selective scan over transposed operands.
// t = ((b*NCH + c)*D_INNER + d)*16 + n
// ---------------------------------------------------------------------------
__global__ void scan_pass_a(const float* __restrict__ dtT,
                            const float* __restrict__ xcT,
                            const float* __restrict__ xdbl,
                            const float* __restrict__ A_log,
                            float* __restrict__ Sarr,
                            float* __restrict__ Parr)
{
    const int t = blockIdx.x * 256 + threadIdx.x;
    const int n = t & 15;
    const int g = t >> 4;
    const int d = g & (D_INNER - 1);
    const int c = (g >> 11) & (NCH - 1);
    const int b = g >> 14;

    const float Aval = -__expf(A_log[d * D_STATE + n]);
    const long base = ((long)d << 11) + (b << 10) + c * CHL;
    const float4* dp4 = (const float4*)(dtT + base);
    const float4* xp4 = (const float4*)(xcT + base);
    const float* xdp  = xdbl + ((long)b * LL + c * CHL) * 128 + 64 + n;

    float h = 0.f, Pr = 1.f;
#pragma unroll 4
    for (int q = 0; q < CHL / 4; q++) {
        const float4 dl4 = dp4[q];
        const float4 xc4 = xp4[q];
#pragma unroll
        for (int j = 0; j < 4; j++) {
            const float dl  = (j == 0) ? dl4.x : (j == 1) ? dl4.y : (j == 2) ? dl4.z : dl4.w;
            const float xcv = (j == 0) ? xc4.x : (j == 1) ? xc4.y : (j == 2) ? xc4.z : xc4.w;
            const float Bv  = xdp[(q * 4 + j) * 128];
            const float a   = __expf(dl * Aval);
            Pr *= a;
            h = fmaf(a, h, dl * Bv * xcv);
        }
    }
    Sarr[t] = h;
    Parr[t] = Pr;
}

__global__ void scan_pass_b(const float* __restrict__ Sarr,
                            const float* __restrict__ Parr,
                            float* __restrict__ Hc)
{
    const int t = blockIdx.x * 256 + threadIdx.x;
    const int n = t & 15;
    const int d = (t >> 4) & (D_INNER - 1);
    const int b = t >> 15;
    float H = 0.f;
#pragma unroll
    for (int c = 0; c < NCH; c++) {
        const long idx = ((long)((b * NCH + c) * D_INNER + d) << 4) + n;
        Hc[idx] = H;
        H = fmaf(Parr[idx], H, Sarr[idx]);
    }
}

__global__ void scan_pass_c(const float* __restrict__ dtT,
                            const float* __restrict__ xcT,
                            const float* __restrict__ zT,
                            const float* __restrict__ xdbl,
                            const float* __restrict__ A_log,
                            const float* __restrict__ Dv,
                            const float* __restrict__ Hc,
                            float* __restrict__ yT)
{
    const int t = blockIdx.x * 256 + threadIdx.x;
    const int n = t & 15;
    const int g = t >> 4;
    const int d = g & (D_INNER - 1);
    const int c = (g >> 11) & (NCH - 1);
    const int b = g >> 14;

    const float Aval = -__expf(A_log[d * D_STATE + n]);
    const float Dd   = Dv[d];

    const long base = ((long)d << 11) + (b << 10) + c * CHL;
    const float4* dp4 = (const float4*)(dtT + base);
    const float4* xp4 = (const float4*)(xcT + base);
    const float4* zp4 = (const float4*)(zT + base);
    const float* xdp  = xdbl + ((long)b * LL + c * CHL) * 128 + 64 + n;
    float* yp = yT + base;

    float h = Hc[t];
    for (int q = 0; q < CHL / 4; q++) {
        const float4 dl4 = dp4[q];
        const float4 xc4 = xp4[q];
        const float4 zv4 = zp4[q];
#pragma unroll
        for (int j = 0; j < 4; j++) {
            const float dl  = (j == 0) ? dl4.x : (j == 1) ? dl4.y : (j == 2) ? dl4.z : dl4.w;
            const float xcv = (j == 0) ? xc4.x : (j == 1) ? xc4.y : (j == 2) ? xc4.z : xc4.w;
            const float zv  = (j == 0) ? zv4.x : (j == 1) ? zv4.y : (j == 2) ? zv4.z : zv4.w;
            const float Bv  = xdp[(q * 4 + j) * 128];
            const float Cv  = xdp[(q * 4 + j) * 128 + 16];

            const float a = __expf(dl * Aval);
            h = fmaf(a, h, dl * Bv * xcv);

            float p = h * Cv;
            p += __shfl_xor_sync(0xffffffffu, p, 8);
            p += __shfl_xor_sync(0xffffffffu, p, 4);
            p += __shfl_xor_sync(0xffffffffu, p, 2);
            p += __shfl_xor_sync(0xffffffffu, p, 1);

            if (n == 0) {
                const float sig = 1.f / (1.f + __expf(-zv));
                yp[q * 4 + j] = (p + xcv * Dd) * (zv * sig);
            }
        }
    }
}

// ---------------------------------------------------------------------------
// out_proj split-K=2 final reduce
// ---------------------------------------------------------------------------
__global__ void reduce_out(const float* __restrict__ p, float* __restrict__ o)
{
    const int n4 = BL * D_MODEL / 4;
    const int i = blockIdx.x * 256 + threadIdx.x;
    if (i >= n4) return;
    const float4 a = ((const float4*)p)[i];
    const float4 b = ((const float4*)p)[n4 + i];
    ((float4*)o)[i] = make_float4(a.x + b.x, a.y + b.y, a.z + b.z, a.w + b.w);
}

// ---------------------------------------------------------------------------
// Launch
// ---------------------------------------------------------------------------
extern "C" void kernel_launch(void* const* d_in, const int* in_sizes, int n_in,
                              void* d_out, int out_size)
{
    const float* x         = (const float*)d_in[0];
    const float* in_proj_w = (const float*)d_in[1];
    const float* conv_w    = (const float*)d_in[2];
    const float* conv_b    = (const float*)d_in[3];
    const float* x_proj_w  = (const float*)d_in[4];
    const float* dt_proj_w = (const float*)d_in[5];
    const float* dt_proj_b = (const float*)d_in[6];
    const float* A_log     = (const float*)d_in[7];
    const float* Dv        = (const float*)d_in[8];
    const float* out_proj  = (const float*)d_in[9];
    float* out = (float*)d_out;

    float *xzT, *xcT, *xpart, *xdbl, *deltaT, *yT, *Sarr, *Parr, *Hc, *opart;
    __nv_bfloat16 *xcs, *dtA, *ys, *xs, *wi, *wo, *wx, *wdt;
    cudaGetSymbolAddress((void**)&xzT,    g_xzT);
    cudaGetSymbolAddress((void**)&xcT,    g_xcT);
    cudaGetSymbolAddress((void**)&xcs,    g_xcs);
    cudaGetSymbolAddress((void**)&xpart,  g_xpart);
    cudaGetSymbolAddress((void**)&xdbl,   g_xdbl);
    cudaGetSymbolAddress((void**)&dtA,    g_dtA);
    cudaGetSymbolAddress((void**)&deltaT, g_deltaT);
    cudaGetSymbolAddress((void**)&yT,     g_yT);
    cudaGetSymbolAddress((void**)&ys,     g_ys);
    cudaGetSymbolAddress((void**)&xs,     g_xs);
    cudaGetSymbolAddress((void**)&wi,     g_wi);
    cudaGetSymbolAddress((void**)&wo,     g_wo);
    cudaGetSymbolAddress((void**)&wx,     g_wx);
    cudaGetSymbolAddress((void**)&wdt,    g_wdt);
    cudaGetSymbolAddress((void**)&Sarr,   g_S);
    cudaGetSymbolAddress((void**)&Parr,   g_P);
    cudaGetSymbolAddress((void**)&Hc,     g_Hc);
    cudaGetSymbolAddress((void**)&opart,  g_opart);

    const int SMEM_SZ = 6 * 16384;   // 96 KB -> 2 CTAs/SM
    static bool attr_set = false;
    if (!attr_set) {
        cudaFuncSetAttribute(hgemm<0>, cudaFuncAttributeMaxDynamicSharedMemorySize, SMEM_SZ);
        cudaFuncSetAttribute(hgemm<2>, cudaFuncAttributeMaxDynamicSharedMemorySize, SMEM_SZ);
        attr_set = true;
    }

    // launch 0-2: operand splits
    split_kernel<1><<<(BL * 1024 / 4 + 255) / 256, 256>>>(x, xs, 1024, BL * 1024 / 4, BL);
    split_kernel<0><<<(4096 * 1024 / 4 + 255) / 256, 256>>>(in_proj_w, wi, 1024, 4096 * 1024 / 4, 4096);
    split_rest<<<(N4_WO + N4_WX + N4_WDT + 255) / 256, 256>>>(
        out_proj, x_proj_w, dt_proj_w, wo, wx, wdt);

    // launch 3 (profiled): xzT = in_proj_w @ x.T  (M=4096 ch, N=2048 tok, K'=3072)
    hgemm<0><<<dim3(16, 32, 1), 512, SMEM_SZ>>>(
        wi, xs, xzT, 3072, 3072, BL, 48, 0, nullptr);

    // launch 4: conv + silu in transposed layout
    conv_silu_T<<<(D_INNER * BL + 255) / 256, 256>>>(xzT, conv_w, conv_b, xcT);

    // launch 5: xcT -> xcs (act-split for x_proj)
    splitT<<<dim3(64, 64), dim3(32, 8)>>>(xcT, xcs);

    // launch 6-7: x_dbl = xc @ x_proj_w.T (split-K=16) + reduce
    hgemm<0><<<dim3(1, 16, KS), 512, SMEM_SZ>>>(
        xcs, wx, xpart, 6144, 6144, 128, 6144 / KS / 64, (long)BL * 128, nullptr);
    reduce_split<<<(BL * 128 / 4 + 255) / 256, 256>>>(xpart, xdbl, dtA);

    // launch 8: deltaT = softplus(dt_proj_w @ dt.T + b)  (M=2048 ch, N=2048 tok)
    hgemm<2><<<dim3(16, 16, 1), 512, SMEM_SZ>>>(
        wdt, dtA, deltaT, 192, 192, BL, 3, 0, dt_proj_b);

    // launch 9-11: chunked selective scan (zT = rows 2048.. of xzT)
    scan_pass_a<<<BB * NCH * D_INNER * D_STATE / 256, 256>>>(
        deltaT, xcT, xdbl, A_log, Sarr, Parr);
    scan_pass_b<<<BB * D_INNER * D_STATE / 256, 256>>>(Sarr, Parr, Hc);
    scan_pass_c<<<BB * NCH * D_INNER * D_STATE / 256, 256>>>(
        deltaT, xcT, xzT + (long)2048 * BL, xdbl, A_log, Dv, Hc, yT);

    // launch 12: yT -> ys (act-split for out_proj)
    splitT<<<dim3(64, 64), dim3(32, 8)>>>(yT, ys);

    // launch 13-14: out = y @ out_proj_w.T (split-K=2) + reduce
    hgemm<0><<<dim3(8, 16, 2), 512, SMEM_SZ>>>(
        ys, wo, opart, 6144, 6144, 1024, 48, (long)BL * D_MODEL, nullptr);
    reduce_out<<<(BL * D_MODEL / 4 + 255) / 256, 256>>>(opart, out);
}

// round 11
// speedup vs baseline: 2.8147x; 1.0419x over previous
#include <cuda_runtime.h>
#include <cuda_bf16.h>
#include <math.h>
#include <stdint.h>

// Problem constants
#define D_MODEL 1024
#define D_INNER 2048
#define D_STATE 16
#define DT_RANK 64
#define D_CONV  4
#define BB      2
#define LL      1024
#define BL      (BB * LL)                 // 2048 tokens
#define KS      16                        // split-K for x_proj
#define NCH     32                        // scan chunks per sequence
#define CHL     (LL / NCH)                // 32 steps per chunk

// ---------------------------------------------------------------------------
// Device scratch. 3-segment K-concat split (K' = 3K):
//   act-style: [hi | lo | hi], wt-style: [hi | hi | lo]
// Transposed dataflow: xzT/xcT/deltaT/yT are [channel][token].
// ---------------------------------------------------------------------------
__device__ float          g_xzT[4096 * BL];
__device__ float          g_xcT[D_INNER * BL];
__device__ __nv_bfloat16  g_xcs[BL * 6144];
__device__ float          g_xpart[KS * BL * 128];
__device__ float          g_xdbl[BL * 128];
__device__ __nv_bfloat16  g_dtA[BL * 192];
__device__ float          g_deltaT[D_INNER * BL];
__device__ float          g_yT[D_INNER * BL];
__device__ __nv_bfloat16  g_ys[BL * 6144];
__device__ __nv_bfloat16  g_xs[BL * 3072];
__device__ __nv_bfloat16  g_wi[4096 * 3072];
__device__ __nv_bfloat16  g_wo[1024 * 6144];
__device__ __nv_bfloat16  g_wx[128 * 6144];
__device__ __nv_bfloat16  g_wdt[2048 * 192];
// chunked-scan intermediates, t = ((b*NCH+c)*D_INNER+d)*16+n
__device__ float          g_S[BB * NCH * D_INNER * D_STATE];
__device__ float          g_P[BB * NCH * D_INNER * D_STATE];
__device__ float          g_Hc[BB * NCH * D_INNER * D_STATE];
// out_proj split-K partials
__device__ float          g_opart[2 * BL * D_MODEL];

// ---------------------------------------------------------------------------
// helpers
// ---------------------------------------------------------------------------
__device__ __forceinline__ void cvt_pair(float x, float y,
                                         uint32_t& hi, uint32_t& lo) {
    asm("cvt.rn.bf16x2.f32 %0, %1, %2;" : "=r"(hi) : "f"(y), "f"(x));
    const float hx = __uint_as_float(hi << 16);
    const float hy = __uint_as_float(hi & 0xFFFF0000u);
    asm("cvt.rn.bf16x2.f32 %0, %1, %2;" : "=r"(lo) : "f"(y - hy), "f"(x - hx));
}

__device__ __forceinline__ void cp16(uint32_t s, const void* g) {
    asm volatile("cp.async.cg.shared.global [%0], [%1], 16;" :: "r"(s), "l"(g));
}
__device__ __forceinline__ void cp_commit() {
    asm volatile("cp.async.commit_group;");
}
__device__ __forceinline__ void cp_wait1() {
    asm volatile("cp.async.wait_group 1;" ::: "memory");
}

#define LDSM_X4(r0, r1, r2, r3, addr) \
    asm volatile("ldmatrix.sync.aligned.m8n8.x4.shared.b16 {%0,%1,%2,%3}, [%4];" \
                 : "=r"(r0), "=r"(r1), "=r"(r2), "=r"(r3) : "r"(addr))

__device__ __forceinline__ void mma_bf16(float (&c)[4],
                                         uint32_t a0, uint32_t a1,
                                         uint32_t a2, uint32_t a3,
                                         uint32_t b0, uint32_t b1) {
    asm volatile(
        "mma.sync.aligned.m16n8k16.row.col.f32.bf16.bf16.f32 "
        "{%0,%1,%2,%3},{%4,%5,%6,%7},{%8,%9},{%0,%1,%2,%3};"
        : "+f"(c[0]), "+f"(c[1]), "+f"(c[2]), "+f"(c[3])
        : "r"(a0), "r"(a1), "r"(a2), "r"(a3), "r"(b0), "r"(b1));
}

// ---------------------------------------------------------------------------
// bf16 HGEMM (pre-split operands), BM=BN=128, BK=64, 512 thr, 3-stage ring.
// EPI==1: +bias[col], softplus.  EPI==2: +bias[row], softplus (swapped GEMMs).
// Split-K via blockIdx.z. Requires M%128==0, N%128==0, K'%64==0/split, T>=2.
// ---------------------------------------------------------------------------
template<int EPI>
__global__ void __launch_bounds__(512, 2)
hgemm(const __nv_bfloat16* __restrict__ A, const __nv_bfloat16* __restrict__ W,
      float* __restrict__ C, int lda, int ldw, int ldc, int T,
      long czstride, const float* __restrict__ bias)
{
    constexpr int S = 3;
    extern __shared__ __align__(16) char smem[];
    const uint32_t smA0 = (uint32_t)__cvta_generic_to_shared(smem);
    const uint32_t smB0 = smA0 + S * 16384;

    const int tid  = threadIdx.x;
    const int wid  = tid >> 5;
    const int lane = tid & 31;
    const int wm   = wid >> 2;
    const int wn   = wid & 3;
    const int l16  = lane & 15;
    const int chal = lane >> 4;

    const long blockM = (long)blockIdx.y * 128;
    const long blockN = (long)blockIdx.x * 128;
    const int  koff   = blockIdx.z * T * 64;

    const __nv_bfloat16* Ab = A + blockM * lda + koff;
    const __nv_bfloat16* Wb = W + blockN * ldw + koff;

    const int crow = tid >> 3;
    const int ccc  = tid & 7;

    uint32_t aoff[2], asw[2], boff[2], bsw[2];
#pragma unroll
    for (int mi = 0; mi < 2; mi++) {
        const int r = wm * 32 + mi * 16 + l16;
        aoff[mi] = r * 128;
        asw[mi]  = r & 7;
    }
#pragma unroll
    for (int ni = 0; ni < 2; ni++) {
        const int r = wn * 32 + ni * 16 + l16;
        boff[ni] = r * 128;
        bsw[ni]  = r & 7;
    }

    float acc[2][4][4];
#pragma unroll
    for (int mi = 0; mi < 2; mi++)
#pragma unroll
        for (int n8 = 0; n8 < 4; n8++)
#pragma unroll
            for (int j = 0; j < 4; j++) acc[mi][n8][j] = 0.f;

    auto issue = [&](int s, int t) {
        const int k0 = t * 64;
        const uint32_t dA = smA0 + s * 16384;
        const uint32_t dB = smB0 + s * 16384;
#pragma unroll
        for (int p = 0; p < 2; p++) {
            const int row = crow + p * 64;
            const int scc = ccc ^ (row & 7);
            cp16(dA + row * 128 + scc * 16, Ab + (long)row * lda + k0 + ccc * 8);
            cp16(dB + row * 128 + scc * 16, Wb + (long)row * ldw + k0 + ccc * 8);
        }
    };

    issue(0, 0);
    cp_commit();
    issue(1, 1);
    cp_commit();

    for (int t = 0; t < T; t++) {
        cp_wait1();
        __syncthreads();
        const int nt = t + 2;
        if (nt < T) issue(nt % S, nt);
        cp_commit();

        const uint32_t sA = smA0 + (t % S) * 16384;
        const uint32_t sB = smB0 + (t % S) * 16384;
#pragma unroll
        for (int k16 = 0; k16 < 4; k16++) {
            const uint32_t ch = (uint32_t)(k16 * 2 + chal);
            uint32_t a[2][4], b[2][4];
#pragma unroll
            for (int mi = 0; mi < 2; mi++)
                LDSM_X4(a[mi][0], a[mi][1], a[mi][2], a[mi][3],
                        sA + aoff[mi] + ((ch ^ asw[mi]) << 4));
#pragma unroll
            for (int ni = 0; ni < 2; ni++)
                LDSM_X4(b[ni][0], b[ni][1], b[ni][2], b[ni][3],
                        sB + boff[ni] + ((ch ^ bsw[ni]) << 4));
#pragma unroll
            for (int mi = 0; mi < 2; mi++)
#pragma unroll
                for (int n8 = 0; n8 < 4; n8++) {
                    const int np = n8 >> 1;
                    const uint32_t b0 = (n8 & 1) ? b[np][1] : b[np][0];
                    const uint32_t b1 = (n8 & 1) ? b[np][3] : b[np][2];
                    mma_bf16(acc[mi][n8],
                             a[mi][0], a[mi][1], a[mi][2], a[mi][3], b0, b1);
                }
        }
    }

    float* Cb = C + (long)blockIdx.z * czstride;
    const int er = lane >> 2;
    const int ec = (lane & 3) * 2;
#pragma unroll
    for (int mi = 0; mi < 2; mi++) {
#pragma unroll
        for (int n8 = 0; n8 < 4; n8++) {
            const long row = blockM + wm * 32 + mi * 16 + er;
            const int  col = (int)blockN + wn * 32 + n8 * 8 + ec;
            float v0 = acc[mi][n8][0], v1 = acc[mi][n8][1];
            float v2 = acc[mi][n8][2], v3 = acc[mi][n8][3];
            if (EPI == 1) {
                const float b0 = bias[col], b1 = bias[col + 1];
                v0 += b0; v1 += b1; v2 += b0; v3 += b1;
                v0 = (v0 > 20.f) ? v0 : log1pf(expf(v0));
                v1 = (v1 > 20.f) ? v1 : log1pf(expf(v1));
                v2 = (v2 > 20.f) ? v2 : log1pf(expf(v2));
                v3 = (v3 > 20.f) ? v3 : log1pf(expf(v3));
            } else if (EPI == 2) {
                const float br = bias[row], br8 = bias[row + 8];
                v0 += br; v1 += br; v2 += br8; v3 += br8;
                v0 = (v0 > 20.f) ? v0 : log1pf(expf(v0));
                v1 = (v1 > 20.f) ? v1 : log1pf(expf(v1));
                v2 = (v2 > 20.f) ? v2 : log1pf(expf(v2));
                v3 = (v3 > 20.f) ? v3 : log1pf(expf(v3));
            }
            *(float2*)&Cb[row * ldc + col]       = make_float2(v0, v1);
            *(float2*)&Cb[(row + 8) * ldc + col] = make_float2(v2, v3);
        }
    }
}

// ---------------------------------------------------------------------------
// f32 -> bf16 3-segment split core
// ---------------------------------------------------------------------------
__device__ __forceinline__ void split_body(const float* __restrict__ in,
                                           __nv_bfloat16* __restrict__ out,
                                           int K, int li, int inRows, int act)
{
    const int e   = li * 4;
    const int row = e / K;
    const int k   = e - row * K;
    float4 v = make_float4(0.f, 0.f, 0.f, 0.f);
    if (row < inRows) v = *(const float4*)(in + (long)row * K + k);
    uint32_t h01, l01, h23, l23;
    cvt_pair(v.x, v.y, h01, l01);
    cvt_pair(v.z, v.w, h23, l23);
    __nv_bfloat16* o = out + (long)row * 3 * K + k;
    const uint2 hv = make_uint2(h01, h23);
    const uint2 lv = make_uint2(l01, l23);
    if (act) {
        *(uint2*)o           = hv;
        *(uint2*)(o + K)     = lv;
        *(uint2*)(o + 2 * K) = hv;
    } else {
        *(uint2*)o           = hv;
        *(uint2*)(o + K)     = hv;
        *(uint2*)(o + 2 * K) = lv;
    }
}

// One kernel splits ALL five operands (x, in_proj_w, out_proj_w, x_proj_w, dt_proj_w)
#define N4_X   (BL * 1024 / 4)
#define N4_WI  (4096 * 1024 / 4)
#define N4_WO  (1024 * 2048 / 4)
#define N4_WX  (128 * 2048 / 4)
#define N4_WDT (2048 * 64 / 4)
__global__ void split_all(const float* __restrict__ x_in,
                          const float* __restrict__ wi_in,
                          const float* __restrict__ wo_in,
                          const float* __restrict__ wx_in,
                          const float* __restrict__ wdt_in,
                          __nv_bfloat16* __restrict__ xs,
                          __nv_bfloat16* __restrict__ wi,
                          __nv_bfloat16* __restrict__ wo,
                          __nv_bfloat16* __restrict__ wx,
                          __nv_bfloat16* __restrict__ wdt)
{
    int i = blockIdx.x * 256 + threadIdx.x;
    if (i < N4_X) { split_body(x_in, xs, 1024, i, BL, 1); return; }
    i -= N4_X;
    if (i < N4_WI) { split_body(wi_in, wi, 1024, i, 4096, 0); return; }
    i -= N4_WI;
    if (i < N4_WO) { split_body(wo_in, wo, 2048, i, 1024, 0); return; }
    i -= N4_WO;
    if (i < N4_WX) { split_body(wx_in, wx, 2048, i, 96, 0); return; }
    i -= N4_WX;
    if (i < N4_WDT) { split_body(wdt_in, wdt, 64, i, 2048, 0); }
}
#define N4_ALL (N4_X + N4_WI + N4_WO + N4_WX + N4_WDT)

// ---------------------------------------------------------------------------
// Split-K reduce for x_proj partials + dt-row act-split
// ---------------------------------------------------------------------------
__global__ void reduce_split(const float* __restrict__ p,
                             float* __restrict__ xdbl,
                             __nv_bfloat16* __restrict__ dtA)
{
    const int n4 = BL * 128 / 4;
    const int i = blockIdx.x * 256 + threadIdx.x;
    if (i >= n4) return;
    float4 a = ((const float4*)p)[i];
#pragma unroll
    for (int s = 1; s < KS; s++) {
        const float4 b = ((const float4*)p)[(long)s * n4 + i];
        a.x += b.x; a.y += b.y; a.z += b.z; a.w += b.w;
    }
    ((float4*)xdbl)[i] = a;
    const int e = i * 4;
    const int col = e & 127;
    if (col < 64) {
        const int row = e >> 7;
        uint32_t h01, l01, h23, l23;
        cvt_pair(a.x, a.y, h01, l01);
        cvt_pair(a.z, a.w, h23, l23);
        __nv_bfloat16* o = dtA + (long)row * 192 + col;
        const uint2 hv = make_uint2(h01, h23);
        *(uint2*)o         = hv;
        *(uint2*)(o + 64)  = make_uint2(l01, l23);
        *(uint2*)(o + 128) = hv;
    }
}

// ---------------------------------------------------------------------------
// Depthwise causal conv (k=4) + bias + SiLU in transposed layout, FUSED with
// the act-split transpose: writes xcT [d][token] f32 AND xcs [token][6144].
// 32x32 tiles, block (32,8).
// ---------------------------------------------------------------------------
__global__ void conv_split_T(const float* __restrict__ xzT,
                             const float* __restrict__ cw,
                             const float* __restrict__ cb,
                             float* __restrict__ xcT,
                             __nv_bfloat16* __restrict__ xcs)
{
    __shared__ float tile[32][33];
    const int d0 = blockIdx.x * 32;
    const int r0 = blockIdx.y * 32;
    const int tx = threadIdx.x;

#pragma unroll
    for (int i = threadIdx.y; i < 32; i += 8) {
        const int d  = d0 + i;
        const int tt = r0 + tx;
        const int l  = tt & (LL - 1);
        const float* row = xzT + ((long)d << 11);
        float acc = cb[d];
#pragma unroll
        for (int k = 0; k < D_CONV; k++) {
            const int ll = l - (D_CONV - 1) + k;
            if (ll >= 0)
                acc = fmaf(row[tt - (D_CONV - 1) + k], cw[d * D_CONV + k], acc);
        }
        const float s = acc / (1.f + __expf(-acc));
        xcT[((long)d << 11) + tt] = s;
        tile[i][tx] = s;
    }
    __syncthreads();
#pragma unroll
    for (int i = threadIdx.y; i < 32; i += 8) {
        const float v = tile[tx][i];
        const int row = r0 + i;
        const int d   = d0 + tx;
        const __nv_bfloat16 hh = __float2bfloat16(v);
        __nv_bfloat16* o = xcs + (long)row * 6144 + d;
        o[0]    = hh;
        o[2048] = __float2bfloat16(v - __bfloat162float(hh));
        o[4096] = hh;
    }
}

// ---------------------------------------------------------------------------
// [d][token] f32 -> [token][6144] act-split bf16 (yT -> ys)
// ---------------------------------------------------------------------------
__global__ void splitT(const float* __restrict__ src,
                       __nv_bfloat16* __restrict__ dst)
{
    __shared__ float tile[32][33];
    const int d0 = blockIdx.x * 32;
    const int r0 = blockIdx.y * 32;
#pragma unroll
    for (int i = threadIdx.y; i < 32; i += 8)
        tile[i][threadIdx.x] = src[(long)(d0 + i) * BL + r0 + threadIdx.x];
    __syncthreads();
#pragma unroll
    for (int i = threadIdx.y; i < 32; i += 8) {
        const float v = tile[threadIdx.x][i];
        const int row = r0 + i;
        const int d   = d0 + threadIdx.x;
        const __nv_bfloat16 hh = __float2bfloat16(v);
        __nv_bfloat16* o = dst + (long)row * 6144 + d;
        o[0]    = hh;
        o[2048] = __float2bfloat16(v - __bfloat162float(hh));
        o[4096] = hh;
    }
}

// ---------------------------------------------------------------------------
// Chunked selective scan over transposed operands. NCH=32, CHL=32.
// t = ((b*NCH + c)*D_INNER + d)*16 + n ;  c = (g>>11)&31, b = g>>16
// ---------------------------------------------------------------------------
__global__ void scan_pass_a(const float* __restrict__ dtT,
                            const float* __restrict__ xcT,
                            const float* __restrict__ xdbl,
                            const float* __restrict__ A_log,
                            float* __restrict__ Sarr,
                            float* __restrict__ Parr)
{
    const int t = blockIdx.x * 256 + threadIdx.x;
    const int n = t & 15;
    const int g = t >> 4;
    const int d = g & (D_INNER - 1);
    const int c = (g >> 11) & (NCH - 1);
    const int b = g >> 16;

    const float Aval = -__expf(A_log[d * D_STATE + n]);
    const long base = ((long)d << 11) + (b << 10) + c * CHL;
    const float4* dp4 = (const float4*)(dtT + base);
    const float4* xp4 = (const float4*)(xcT + base);
    const float* xdp  = xdbl + ((long)b * LL + c * CHL) * 128 + 64 + n;

    float h = 0.f, Pr = 1.f;
#pragma unroll
    for (int q = 0; q < CHL / 4; q++) {
        const float4 dl4 = dp4[q];
        const float4 xc4 = xp4[q];
#pragma unroll
        for (int j = 0; j < 4; j++) {
            const float dl  = (j == 0) ? dl4.x : (j == 1) ? dl4.y : (j == 2) ? dl4.z : dl4.w;
            const float xcv = (j == 0) ? xc4.x : (j == 1) ? xc4.y : (j == 2) ? xc4.z : xc4.w;
            const float Bv  = xdp[(q * 4 + j) * 128];
            const float a   = __expf(dl * Aval);
            Pr *= a;
            h = fmaf(a, h, dl * Bv * xcv);
        }
    }
    Sarr[t] = h;
    Parr[t] = Pr;
}

__global__ void scan_pass_b(const float* __restrict__ Sarr,
                            const float* __restrict__ Parr,
                            float* __restrict__ Hc)
{
    const int t = blockIdx.x * 256 + threadIdx.x;
    const int n = t & 15;
    const int d = (t >> 4) & (D_INNER - 1);
    const int b = t >> 15;
    float H = 0.f;
#pragma unroll
    for (int c = 0; c < NCH; c++) {
        const long idx = ((long)((b * NCH + c) * D_INNER + d) << 4) + n;
        Hc[idx] = H;
        H = fmaf(Parr[idx], H, Sarr[idx]);
    }
}

__global__ void scan_pass_c(const float* __restrict__ dtT,
                            const float* __restrict__ xcT,
                            const float* __restrict__ zT,
                            const float* __restrict__ xdbl,
                            const float* __restrict__ A_log,
                            const float* __restrict__ Dv,
                            const float* __restrict__ Hc,
                            float* __restrict__ yT)
{
    const int t = blockIdx.x * 256 + threadIdx.x;
    const int n = t & 15;
    const int g = t >> 4;
    const int d = g & (D_INNER - 1);
    const int c = (g >> 11) & (NCH - 1);
    const int b = g >> 16;

    const float Aval = -__expf(A_log[d * D_STATE + n]);
    const float Dd   = Dv[d];

    const long base = ((long)d << 11) + (b << 10) + c * CHL;
    const float4* dp4 = (const float4*)(dtT + base);
    const float4* xp4 = (const float4*)(xcT + base);
    const float4* zp4 = (const float4*)(zT + base);
    const float* xdp  = xdbl + ((long)b * LL + c * CHL) * 128 + 64 + n;
    float* yp = yT + base;

    float h = Hc[t];
#pragma unroll
    for (int q = 0; q < CHL / 4; q++) {
        const float4 dl4 = dp4[q];
        const float4 xc4 = xp4[q];
        const float4 zv4 = zp4[q];
#pragma unroll
        for (int j = 0; j < 4; j++) {
            const float dl  = (j == 0) ? dl4.x : (j == 1) ? dl4.y : (j == 2) ? dl4.z : dl4.w;
            const float xcv = (j == 0) ? xc4.x : (j == 1) ? xc4.y : (j == 2) ? xc4.z : xc4.w;
            const float zv  = (j == 0) ? zv4.x : (j == 1) ? zv4.y : (j == 2) ? zv4.z : zv4.w;
            const float Bv  = xdp[(q * 4 + j) * 128];
            const float Cv  = xdp[(q * 4 + j) * 128 + 16];

            const float a = __expf(dl * Aval);
            h = fmaf(a, h, dl * Bv * xcv);

            float p = h * Cv;
            p += __shfl_xor_sync(0xffffffffu, p, 8);
            p += __shfl_xor_sync(0xffffffffu, p, 4);
            p += __shfl_xor_sync(0xffffffffu, p, 2);
            p += __shfl_xor_sync(0xffffffffu, p, 1);

            if (n == 0) {
                const float sig = 1.f / (1.f + __expf(-zv));
                yp[q * 4 + j] = (p + xcv * Dd) * (zv * sig);
            }
        }
    }
}

// ---------------------------------------------------------------------------
// out_proj split-K=2 final reduce
// ---------------------------------------------------------------------------
__global__ void reduce_out(const float* __restrict__ p, float* __restrict__ o)
{
    const int n4 = BL * D_MODEL / 4;
    const int i = blockIdx.x * 256 + threadIdx.x;
    if (i >= n4) return;
    const float4 a = ((const float4*)p)[i];
    const float4 b = ((const float4*)p)[n4 + i];
    ((float4*)o)[i] = make_float4(a.x + b.x, a.y + b.y, a.z + b.z, a.w + b.w);
}

// ---------------------------------------------------------------------------
// Launch
// ---------------------------------------------------------------------------
extern "C" void kernel_launch(void* const* d_in, const int* in_sizes, int n_in,
                              void* d_out, int out_size)
{
    const float* x         = (const float*)d_in[0];
    const float* in_proj_w = (const float*)d_in[1];
    const float* conv_w    = (const float*)d_in[2];
    const float* conv_b    = (const float*)d_in[3];
    const float* x_proj_w  = (const float*)d_in[4];
    const float* dt_proj_w = (const float*)d_in[5];
    const float* dt_proj_b = (const float*)d_in[6];
    const float* A_log     = (const float*)d_in[7];
    const float* Dv        = (const float*)d_in[8];
    const float* out_proj  = (const float*)d_in[9];
    float* out = (float*)d_out;

    float *xzT, *xcT, *xpart, *xdbl, *deltaT, *yT, *Sarr, *Parr, *Hc, *opart;
    __nv_bfloat16 *xcs, *dtA, *ys, *xs, *wi, *wo, *wx, *wdt;
    cudaGetSymbolAddress((void**)&xzT,    g_xzT);
    cudaGetSymbolAddress((void**)&xcT,    g_xcT);
    cudaGetSymbolAddress((void**)&xcs,    g_xcs);
    cudaGetSymbolAddress((void**)&xpart,  g_xpart);
    cudaGetSymbolAddress((void**)&xdbl,   g_xdbl);
    cudaGetSymbolAddress((void**)&dtA,    g_dtA);
    cudaGetSymbolAddress((void**)&deltaT, g_deltaT);
    cudaGetSymbolAddress((void**)&yT,     g_yT);
    cudaGetSymbolAddress((void**)&ys,     g_ys);
    cudaGetSymbolAddress((void**)&xs,     g_xs);
    cudaGetSymbolAddress((void**)&wi,     g_wi);
    cudaGetSymbolAddress((void**)&wo,     g_wo);
    cudaGetSymbolAddress((void**)&wx,     g_wx);
    cudaGetSymbolAddress((void**)&wdt,    g_wdt);
    cudaGetSymbolAddress((void**)&Sarr,   g_S);
    cudaGetSymbolAddress((void**)&Parr,   g_P);
    cudaGetSymbolAddress((void**)&Hc,     g_Hc);
    cudaGetSymbolAddress((void**)&opart,  g_opart);

    const int SMEM_SZ = 6 * 16384;   // 96 KB -> 2 CTAs/SM
    static bool attr_set = false;
    if (!attr_set) {
        cudaFuncSetAttribute(hgemm<0>, cudaFuncAttributeMaxDynamicSharedMemorySize, SMEM_SZ);
        cudaFuncSetAttribute(hgemm<2>, cudaFuncAttributeMaxDynamicSharedMemorySize, SMEM_SZ);
        attr_set = true;
    }

    // launch 0: all operand splits in one kernel
    split_all<<<(N4_ALL + 255) / 256, 256>>>(
        x, in_proj_w, out_proj, x_proj_w, dt_proj_w, xs, wi, wo, wx, wdt);

    // launch 1: xzT = in_proj_w @ x.T  (M=4096 ch, N=2048 tok, K'=3072)
    hgemm<0><<<dim3(16, 32, 1), 512, SMEM_SZ>>>(
        wi, xs, xzT, 3072, 3072, BL, 48, 0, nullptr);

    // launch 2: conv + silu + act-split (xcT f32 and xcs bf16)
    conv_split_T<<<dim3(64, 64), dim3(32, 8)>>>(xzT, conv_w, conv_b, xcT, xcs);

    // launch 3 (profiled slot): x_dbl = xc @ x_proj_w.T (split-K=16)
    hgemm<0><<<dim3(1, 16, KS), 512, SMEM_SZ>>>(
        xcs, wx, xpart, 6144, 6144, 128, 6144 / KS / 64, (long)BL * 128, nullptr);
    // launch 4: reduce + dt act-split
    reduce_split<<<(BL * 128 / 4 + 255) / 256, 256>>>(xpart, xdbl, dtA);

    // launch 5: deltaT = softplus(dt_proj_w @ dt.T + b)
    hgemm<2><<<dim3(16, 16, 1), 512, SMEM_SZ>>>(
        wdt, dtA, deltaT, 192, 192, BL, 3, 0, dt_proj_b);

    // launch 6-8: chunked selective scan (NCH=32)
    scan_pass_a<<<BB * NCH * D_INNER * D_STATE / 256, 256>>>(
        deltaT, xcT, xdbl, A_log, Sarr, Parr);
    scan_pass_b<<<BB * D_INNER * D_STATE / 256, 256>>>(Sarr, Parr, Hc);
    scan_pass_c<<<BB * NCH * D_INNER * D_STATE / 256, 256>>>(
        deltaT, xcT, xzT + (long)2048 * BL, xdbl, A_log, Dv, Hc, yT);

    // launch 9: yT -> ys (act-split for out_proj)
    splitT<<<dim3(64, 64), dim3(32, 8)>>>(yT, ys);

    // launch 10-11: out = y @ out_proj_w.T (split-K=2) + reduce
    hgemm<0><<<dim3(8, 16, 2), 512, SMEM_SZ>>>(
        ys, wo, opart, 6144, 6144, 1024, 48, (long)BL * D_MODEL, nullptr);
    reduce_out<<<(BL * D_MODEL / 4 + 255) / 256, 256>>>(opart, out);
}